// round 1
// baseline (speedup 1.0000x reference)
#include <cuda_runtime.h>
#include <math.h>

#define Bn 32
#define Rn 512
#define Dn 256
#define Pn 5532
#define SLOT 512              // max unique labels per image (<= R)
#define NROWS (Bn*Rn)         // 16384

// ---------------- scratch (device globals; no allocations) ----------------
__device__ float g_x[NROWS*Dn];            // scaled features       16 MB
__device__ float g_proto[Bn*SLOT*Dn];      // prototype sums/normed 16 MB
__device__ float g_logits[Bn*Rn*SLOT];     // compacted logits      32 MB
__device__ int   g_cidx[Bn*Pn];            // label -> compact slot (-1 absent)
__device__ int   g_cnt[Bn*SLOT];           // count per slot
__device__ int   g_nuniq[Bn];
__device__ float g_nll[NROWS];

// ---------------- 1: x = inputs * cls ; zero proto ----------------
__global__ void k_scale(const float* __restrict__ inp,
                        const float* __restrict__ cls) {
    int i = blockIdx.x * blockDim.x + threadIdx.x;      // float4 index
    // NROWS*Dn/4 = 1048576 float4s ; Dn/4 = 64 per row
    int row = i >> 6;
    float c = cls[row];
    float4 v = ((const float4*)inp)[i];
    v.x *= c; v.y *= c; v.z *= c; v.w *= c;
    ((float4*)g_x)[i] = v;
    ((float4*)g_proto)[i] = make_float4(0.f, 0.f, 0.f, 0.f);
}

// ---------------- 2: per-image histogram + compaction ----------------
__global__ void k_compact(const int* __restrict__ roi_label) {
    int b = blockIdx.x;
    __shared__ int cnt[Pn];
    __shared__ int scan[257];
    for (int p = threadIdx.x; p < Pn; p += 256) cnt[p] = 0;
    __syncthreads();
    for (int r = threadIdx.x; r < Rn; r += 256) {
        int lab = roi_label[b*Rn + r] - 1;
        if (lab >= 0) atomicAdd(&cnt[lab], 1);
    }
    __syncthreads();
    const int chunk = (Pn + 255) / 256;                 // 22
    int start = threadIdx.x * chunk;
    int local = 0;
    for (int i = 0; i < chunk; i++) {
        int p = start + i;
        if (p < Pn && cnt[p] > 0) local++;
    }
    scan[threadIdx.x + 1] = local;
    if (threadIdx.x == 0) scan[0] = 0;
    __syncthreads();
    if (threadIdx.x == 0) {
        for (int i = 1; i <= 256; i++) scan[i] += scan[i-1];
        g_nuniq[b] = scan[256];
    }
    __syncthreads();
    int off = scan[threadIdx.x];
    for (int i = 0; i < chunk; i++) {
        int p = start + i;
        if (p >= Pn) break;
        if (cnt[p] > 0) {
            g_cidx[b*Pn + p] = off;
            g_cnt[b*SLOT + off] = cnt[p];
            off++;
        } else {
            g_cidx[b*Pn + p] = -1;
        }
    }
}

// ---------------- 3: proto accumulate (one block = one roi) ----------------
__global__ void k_accum(const int* __restrict__ roi_label) {
    int row = blockIdx.x;                               // 0..NROWS-1
    int lab = roi_label[row] - 1;
    if (lab < 0) return;
    int b = row / Rn;
    int j = g_cidx[b*Pn + lab];
    const float4 v = ((const float4*)(g_x + (size_t)row*Dn))[threadIdx.x]; // 64 thr * 4
    float* pr = g_proto + ((size_t)b*SLOT + j)*Dn + threadIdx.x*4;
    atomicAdd(pr+0, v.x);
    atomicAdd(pr+1, v.y);
    atomicAdd(pr+2, v.z);
    atomicAdd(pr+3, v.w);
}

// ---------------- 4: proto normalize (one warp = one slot) ----------------
__global__ void k_norm() {
    int idx  = blockIdx.x * 8 + (threadIdx.x >> 5);     // slot index
    int lane = threadIdx.x & 31;
    int b = idx / SLOT, j = idx % SLOT;
    if (j >= g_nuniq[b]) return;
    float* pr = g_proto + (size_t)idx * Dn;
    float4 v0 = ((float4*)pr)[lane];
    float4 v1 = ((float4*)pr)[lane + 32];
    float ss = v0.x*v0.x + v0.y*v0.y + v0.z*v0.z + v0.w*v0.w
             + v1.x*v1.x + v1.y*v1.y + v1.z*v1.z + v1.w*v1.w;
    #pragma unroll
    for (int o = 16; o > 0; o >>= 1) ss += __shfl_xor_sync(0xffffffffu, ss, o);
    float c = (float)g_cnt[b*SLOT + j];
    float norm_mean = sqrtf(ss) / c;                    // ||sum/c||
    float scale = 1.0f / (c * fmaxf(norm_mean, 1e-12f));
    v0.x*=scale; v0.y*=scale; v0.z*=scale; v0.w*=scale;
    v1.x*=scale; v1.y*=scale; v1.z*=scale; v1.w*=scale;
    ((float4*)pr)[lane] = v0;
    ((float4*)pr)[lane + 32] = v1;
}

// ---------------- 5: logits GEMM  C[r,j] = x[r,:] . proto[j,:] ----------------
// per image: A[512x256] * B[512x256]^T -> C[512x512]; 128x128 tile, K-step 8
__global__ __launch_bounds__(256, 2) void k_gemm() {
    int b = blockIdx.z;
    int jBase = blockIdx.x * 128;
    int rBase = blockIdx.y * 128;
    const float* A  = g_x     + (size_t)b*Rn*Dn;
    const float* Bp = g_proto + (size_t)b*SLOT*Dn;
    float*       C  = g_logits+ (size_t)b*Rn*SLOT;

    __shared__ float As[8][128];
    __shared__ float Bs[8][128];

    int tid = threadIdx.x;
    int tx = tid & 15, ty = tid >> 4;
    int lr = tid >> 1;                // 0..127
    int lk = (tid & 1) * 4;           // 0 or 4

    float acc[8][8];
    #pragma unroll
    for (int i = 0; i < 8; i++)
        #pragma unroll
        for (int j = 0; j < 8; j++) acc[i][j] = 0.f;

    for (int k0 = 0; k0 < Dn; k0 += 8) {
        float4 a4 = *(const float4*)(A  + (size_t)(rBase+lr)*Dn + k0 + lk);
        float4 b4 = *(const float4*)(Bp + (size_t)(jBase+lr)*Dn + k0 + lk);
        __syncthreads();
        As[lk+0][lr]=a4.x; As[lk+1][lr]=a4.y; As[lk+2][lr]=a4.z; As[lk+3][lr]=a4.w;
        Bs[lk+0][lr]=b4.x; Bs[lk+1][lr]=b4.y; Bs[lk+2][lr]=b4.z; Bs[lk+3][lr]=b4.w;
        __syncthreads();
        #pragma unroll
        for (int k = 0; k < 8; k++) {
            float ar[8], br[8];
            *(float4*)(ar)   = *(const float4*)&As[k][ty*8];
            *(float4*)(ar+4) = *(const float4*)&As[k][ty*8+4];
            *(float4*)(br)   = *(const float4*)&Bs[k][tx*8];
            *(float4*)(br+4) = *(const float4*)&Bs[k][tx*8+4];
            #pragma unroll
            for (int i = 0; i < 8; i++)
                #pragma unroll
                for (int j = 0; j < 8; j++)
                    acc[i][j] = fmaf(ar[i], br[j], acc[i][j]);
        }
    }
    #pragma unroll
    for (int i = 0; i < 8; i++) {
        float* crow = C + (size_t)(rBase + ty*8 + i)*SLOT + jBase + tx*8;
        *(float4*)(crow)   = make_float4(acc[i][0], acc[i][1], acc[i][2], acc[i][3]);
        *(float4*)(crow+4) = make_float4(acc[i][4], acc[i][5], acc[i][6], acc[i][7]);
    }
}

// ---------------- 6: online logsumexp + NLL (one warp = one roi) ----------------
__global__ void k_nll(const int* __restrict__ roi_label) {
    int row  = blockIdx.x * 8 + (threadIdx.x >> 5);
    int lane = threadIdx.x & 31;
    int b = row / Rn, r = row % Rn;
    int lab = roi_label[row] - 1;
    int nu = g_nuniq[b];
    const float* L = g_logits + (size_t)b*Rn*SLOT + (size_t)r*SLOT;

    float m = -3.0e38f, s = 0.f;
    for (int j = lane; j < nu; j += 32) {
        float l = L[j];
        float nm = fmaxf(m, l);
        s = s * __expf(m - nm) + __expf(l - nm);
        m = nm;
    }
    #pragma unroll
    for (int o = 16; o > 0; o >>= 1) {
        float om = __shfl_xor_sync(0xffffffffu, m, o);
        float os = __shfl_xor_sync(0xffffffffu, s, o);
        float nm = fmaxf(m, om);
        s = s * __expf(m - nm) + os * __expf(om - nm);
        m = nm;
    }
    if (lane == 0) {
        float out = 0.f;
        if (lab >= 0) {
            int jt = g_cidx[b*Pn + lab];
            float lse = m + logf(s);
            out = lse - L[jt];
        }
        g_nll[row] = out;
    }
}

// ---------------- 7: final reduce ----------------
__global__ void k_reduce(const int* __restrict__ roi_label, float* __restrict__ out) {
    __shared__ float ssum[512];
    __shared__ int   scnt[512];
    float s = 0.f; int c = 0;
    for (int i = threadIdx.x; i < NROWS; i += 512) {
        s += g_nll[i];
        c += (roi_label[i] > 0);
    }
    ssum[threadIdx.x] = s; scnt[threadIdx.x] = c;
    __syncthreads();
    for (int o = 256; o > 0; o >>= 1) {
        if (threadIdx.x < o) {
            ssum[threadIdx.x] += ssum[threadIdx.x + o];
            scnt[threadIdx.x] += scnt[threadIdx.x + o];
        }
        __syncthreads();
    }
    if (threadIdx.x == 0)
        out[0] = ssum[0] / fmaxf((float)scnt[0], 1.0f);
}

extern "C" void kernel_launch(void* const* d_in, const int* in_sizes, int n_in,
                              void* d_out, int out_size) {
    const float* inp = (const float*)d_in[0];
    const float* cls = (const float*)d_in[1];
    const int*   lab = (const int*)d_in[2];
    float* out = (float*)d_out;

    k_scale<<<(NROWS*Dn/4 + 255)/256, 256>>>(inp, cls);
    k_compact<<<Bn, 256>>>(lab);
    k_accum<<<NROWS, 64>>>(lab);
    k_norm<<<(Bn*SLOT)/8, 256>>>();
    k_gemm<<<dim3(SLOT/128, Rn/128, Bn), 256>>>();
    k_nll<<<NROWS/8, 256>>>(lab);
    k_reduce<<<1, 512>>>(lab, out);
}

// round 5
// speedup vs baseline: 1.0858x; 1.0858x over previous
#include <cuda_runtime.h>
#include <cuda_bf16.h>
#include <cstdint>
#include <math.h>

#define Bn 32
#define Rn 512
#define Dn 256
#define Pn 5532
#define SLOT 512
#define NROWS (Bn*Rn)
#define PAD 72                 // bf16 row stride in smem (64 + 8)

// ---------------- scratch ----------------
__device__ __align__(16) __nv_bfloat16 g_xh[NROWS*Dn];       // scaled feats bf16  8MB
__device__ __align__(16) __nv_bfloat16 g_ph[Bn*SLOT*Dn];     // normed protos bf16 8MB
__device__ float g_logits[(size_t)Bn*Rn*SLOT];               // compacted logits  32MB
__device__ int   g_rslot[NROWS];                             // roi -> slot (-1 bg)
__device__ int   g_nuniq[Bn];
__device__ float g_nll[NROWS];

// ---------------- helpers ----------------
__device__ __forceinline__ uint32_t smem_u32(const void* p) {
    uint32_t a;
    asm("{ .reg .u64 t; cvta.to.shared.u64 t, %1; cvt.u32.u64 %0, t; }" : "=r"(a) : "l"(p));
    return a;
}
__device__ __forceinline__ void ldm_x4(uint32_t* r, uint32_t addr) {
    asm volatile("ldmatrix.sync.aligned.m8n8.x4.shared.b16 {%0,%1,%2,%3}, [%4];"
        : "=r"(r[0]), "=r"(r[1]), "=r"(r[2]), "=r"(r[3]) : "r"(addr));
}
__device__ __forceinline__ void mma_bf16(float* c, const uint32_t* a, uint32_t b0, uint32_t b1) {
    asm volatile(
        "mma.sync.aligned.m16n8k16.row.col.f32.bf16.bf16.f32 "
        "{%0,%1,%2,%3}, {%4,%5,%6,%7}, {%8,%9}, {%0,%1,%2,%3};"
        : "+f"(c[0]), "+f"(c[1]), "+f"(c[2]), "+f"(c[3])
        : "r"(a[0]), "r"(a[1]), "r"(a[2]), "r"(a[3]), "r"(b0), "r"(b1));
}
__device__ __forceinline__ unsigned long long pack4bf(float a, float b, float c, float d) {
    __nv_bfloat162 lo = __floats2bfloat162_rn(a, b);
    __nv_bfloat162 hi = __floats2bfloat162_rn(c, d);
    unsigned int l = *reinterpret_cast<unsigned int*>(&lo);
    unsigned int h = *reinterpret_cast<unsigned int*>(&hi);
    return (unsigned long long)l | ((unsigned long long)h << 32);
}

// ---------------- 1: g_xh = bf16(inputs * cls) ----------------
__global__ void k_scale(const float* __restrict__ inp, const float* __restrict__ cls) {
    int i = blockIdx.x * 256 + threadIdx.x;      // float4 index; Dn/4=64 per row
    int row = i >> 6;
    float c = cls[row];
    float4 v = ((const float4*)inp)[i];
    ((unsigned long long*)g_xh)[i] = pack4bf(v.x * c, v.y * c, v.z * c, v.w * c);
}

// ---------------- 2: per-image histogram + compaction -> rslot ----------------
__global__ void k_compact(const int* __restrict__ roi_label) {
    int b = blockIdx.x;
    __shared__ int cnt[Pn];
    __shared__ int scan[257];
    for (int p = threadIdx.x; p < Pn; p += 256) cnt[p] = 0;
    __syncthreads();
    for (int r = threadIdx.x; r < Rn; r += 256) {
        int lab = roi_label[b*Rn + r] - 1;
        if (lab >= 0) atomicAdd(&cnt[lab], 1);
    }
    __syncthreads();
    const int chunk = (Pn + 255) / 256;   // 22
    int start = threadIdx.x * chunk;
    int local = 0;
    for (int i = 0; i < chunk; i++) {
        int p = start + i;
        if (p < Pn && cnt[p] > 0) local++;
    }
    scan[threadIdx.x + 1] = local;
    if (threadIdx.x == 0) scan[0] = 0;
    __syncthreads();
    if (threadIdx.x == 0) {
        for (int i = 1; i <= 256; i++) scan[i] += scan[i-1];
        g_nuniq[b] = scan[256];
    }
    __syncthreads();
    int off = scan[threadIdx.x];
    for (int i = 0; i < chunk; i++) {
        int p = start + i;
        if (p >= Pn) break;
        int c = cnt[p];
        cnt[p] = (c > 0) ? off : -1;      // overwrite count with slot id
        if (c > 0) off++;
    }
    __syncthreads();
    for (int r = threadIdx.x; r < Rn; r += 256) {
        int lab = roi_label[b*Rn + r] - 1;
        g_rslot[b*Rn + r] = (lab >= 0) ? cnt[lab] : -1;
    }
}

// ---------------- 3: prototypes (one warp = one slot; deterministic scan) ----------------
__global__ void k_proto(const float* __restrict__ inp, const float* __restrict__ cls) {
    int b    = blockIdx.x >> 6;           // 64 groups of 8 slots per image
    int grp  = blockIdx.x & 63;
    int wid  = threadIdx.x >> 5;
    int lane = threadIdx.x & 31;
    int j = grp * 8 + wid;
    __shared__ int rs[Rn];
    for (int r = threadIdx.x; r < Rn; r += 256) rs[r] = g_rslot[b*Rn + r];
    __syncthreads();
    size_t prow = ((size_t)b*SLOT + j) * Dn;
    if (j >= g_nuniq[b]) {                // zero unused proto rows (deterministic)
        ((uint4*)(g_ph + prow))[lane] = make_uint4(0, 0, 0, 0);
        return;
    }
    float4 s0 = make_float4(0,0,0,0), s1 = make_float4(0,0,0,0);
    int c = 0;
    for (int r = 0; r < Rn; r++) {
        if (rs[r] == j) {
            c++;
            const float* xr = inp + ((size_t)b*Rn + r) * Dn;
            float cc = cls[b*Rn + r];
            float4 a = ((const float4*)xr)[lane];
            float4 q = ((const float4*)xr)[lane + 32];
            s0.x += a.x*cc; s0.y += a.y*cc; s0.z += a.z*cc; s0.w += a.w*cc;
            s1.x += q.x*cc; s1.y += q.y*cc; s1.z += q.z*cc; s1.w += q.w*cc;
        }
    }
    float ss = s0.x*s0.x + s0.y*s0.y + s0.z*s0.z + s0.w*s0.w
             + s1.x*s1.x + s1.y*s1.y + s1.z*s1.z + s1.w*s1.w;
    #pragma unroll
    for (int o = 16; o > 0; o >>= 1) ss += __shfl_xor_sync(0xffffffffu, ss, o);
    float cf = (float)c;
    float scale = 1.0f / (cf * fmaxf(sqrtf(ss) / cf, 1e-12f));
    unsigned long long* dst = (unsigned long long*)(g_ph + prow);
    dst[lane]      = pack4bf(s0.x*scale, s0.y*scale, s0.z*scale, s0.w*scale);
    dst[lane + 32] = pack4bf(s1.x*scale, s1.y*scale, s1.z*scale, s1.w*scale);
}

// ---------------- 4: bf16 mma.sync GEMM  C[128,128] tile per CTA ----------------
// 8 warps, each 64x32; K=256 in 4 chunks of 64
__global__ __launch_bounds__(256, 2) void k_gemm_mma() {
    __shared__ __nv_bfloat16 sA[128*PAD];
    __shared__ __nv_bfloat16 sB[128*PAD];
    int tid = threadIdx.x;
    int warp = tid >> 5, lane = tid & 31;
    int b = blockIdx.z;
    int rBase = blockIdx.y * 128;
    int jBase = blockIdx.x * 128;
    const __nv_bfloat16* A  = g_xh + ((size_t)b*Rn   + rBase) * Dn;
    const __nv_bfloat16* Bp = g_ph + ((size_t)b*SLOT + jBase) * Dn;

    int wm = (warp >> 2) * 64;      // 0 / 64
    int wn = (warp & 3) * 32;       // 0 / 32 / 64 / 96

    float acc[4][4][4];
    #pragma unroll
    for (int mt = 0; mt < 4; mt++)
        #pragma unroll
        for (int nt = 0; nt < 4; nt++)
            #pragma unroll
            for (int q = 0; q < 4; q++) acc[mt][nt][q] = 0.f;

    uint32_t sAu = smem_u32(sA), sBu = smem_u32(sB);

    // ldmatrix lane addressing (constant across ksteps up to k offset)
    int aRow = (lane & 15);
    int aColOff = (lane >> 4) * 8;
    int bN = (lane & 7) + ((lane >> 4) << 3);
    int bKOff = ((lane >> 3) & 1) * 8;

    for (int kc = 0; kc < 4; kc++) {
        int k0 = kc * 64;
        #pragma unroll
        for (int i = tid; i < 1024; i += 256) {   // 128 rows x 8 uint4
            int row = i >> 3, c = i & 7;
            *(uint4*)&sA[row*PAD + c*8] = *(const uint4*)(A  + (size_t)row*Dn + k0 + c*8);
            *(uint4*)&sB[row*PAD + c*8] = *(const uint4*)(Bp + (size_t)row*Dn + k0 + c*8);
        }
        __syncthreads();
        #pragma unroll
        for (int ks = 0; ks < 4; ks++) {
            int kk = ks * 16;
            uint32_t a[4][4];
            #pragma unroll
            for (int mt = 0; mt < 4; mt++) {
                int row = wm + mt*16 + aRow;
                ldm_x4(a[mt], sAu + (row*PAD + kk + aColOff) * 2);
            }
            uint32_t bb[2][4];
            #pragma unroll
            for (int p = 0; p < 2; p++) {
                int n = wn + p*16 + bN;
                ldm_x4(bb[p], sBu + (n*PAD + kk + bKOff) * 2);
            }
            #pragma unroll
            for (int mt = 0; mt < 4; mt++)
                #pragma unroll
                for (int nt = 0; nt < 4; nt++)
                    mma_bf16(acc[mt][nt], a[mt],
                             bb[nt >> 1][(nt & 1)*2], bb[nt >> 1][(nt & 1)*2 + 1]);
        }
        __syncthreads();
    }

    float* C = g_logits + ((size_t)b*Rn + rBase) * SLOT + jBase;
    int tg = lane >> 2, ti = lane & 3;
    #pragma unroll
    for (int mt = 0; mt < 4; mt++) {
        #pragma unroll
        for (int nt = 0; nt < 4; nt++) {
            int row0 = wm + mt*16 + tg;
            int col  = wn + nt*8 + ti*2;
            *(float2*)&C[(size_t)row0*SLOT + col]     = make_float2(acc[mt][nt][0], acc[mt][nt][1]);
            *(float2*)&C[(size_t)(row0+8)*SLOT + col] = make_float2(acc[mt][nt][2], acc[mt][nt][3]);
        }
    }
}

// ---------------- 5: online logsumexp + NLL (one warp per roi) ----------------
__global__ void k_nll() {
    int row  = blockIdx.x * 8 + (threadIdx.x >> 5);
    int lane = threadIdx.x & 31;
    int b = row / Rn, r = row % Rn;
    int jt = g_rslot[row];
    int nu = g_nuniq[b];
    const float* L = g_logits + ((size_t)b*Rn + r) * SLOT;

    float m = -3.0e38f, s = 0.f;
    for (int j = lane; j < nu; j += 32) {
        float l = L[j];
        float nm = fmaxf(m, l);
        s = s * __expf(m - nm) + __expf(l - nm);
        m = nm;
    }
    #pragma unroll
    for (int o = 16; o > 0; o >>= 1) {
        float om = __shfl_xor_sync(0xffffffffu, m, o);
        float os = __shfl_xor_sync(0xffffffffu, s, o);
        float nm = fmaxf(m, om);
        s = s * __expf(m - nm) + os * __expf(om - nm);
        m = nm;
    }
    if (lane == 0) {
        float out = 0.f;
        if (jt >= 0) out = (m + logf(s)) - L[jt];
        g_nll[row] = out;
    }
}

// ---------------- 6: final reduce ----------------
__global__ void k_reduce(const int* __restrict__ roi_label, float* __restrict__ out) {
    __shared__ float ssum[512];
    __shared__ int   scnt[512];
    float s = 0.f; int c = 0;
    for (int i = threadIdx.x; i < NROWS; i += 512) {
        s += g_nll[i];
        c += (roi_label[i] > 0);
    }
    ssum[threadIdx.x] = s; scnt[threadIdx.x] = c;
    __syncthreads();
    for (int o = 256; o > 0; o >>= 1) {
        if (threadIdx.x < o) {
            ssum[threadIdx.x] += ssum[threadIdx.x + o];
            scnt[threadIdx.x] += scnt[threadIdx.x + o];
        }
        __syncthreads();
    }
    if (threadIdx.x == 0)
        out[0] = ssum[0] / fmaxf((float)scnt[0], 1.0f);
}

extern "C" void kernel_launch(void* const* d_in, const int* in_sizes, int n_in,
                              void* d_out, int out_size) {
    const float* inp = (const float*)d_in[0];
    const float* cls = (const float*)d_in[1];
    const int*   lab = (const int*)d_in[2];
    float* out = (float*)d_out;

    k_scale<<<NROWS*Dn/4/256, 256>>>(inp, cls);
    k_compact<<<Bn, 256>>>(lab);
    k_proto<<<Bn*64, 256>>>(inp, cls);
    k_gemm_mma<<<dim3(SLOT/128, Rn/128, Bn), 256>>>();
    k_nll<<<NROWS/8, 256>>>();
    k_reduce<<<1, 512>>>(lab, out);
}

// round 6
// speedup vs baseline: 2.5563x; 2.3543x over previous
#include <cuda_runtime.h>
#include <cuda_bf16.h>
#include <cstdint>
#include <math.h>

#define Bn 32
#define Rn 512
#define Dn 256
#define Pn 5532
#define SLOT 512
#define NROWS (Bn*Rn)
#define PAD 72                 // bf16 row stride in smem (64 + 8)

// ---------------- scratch ----------------
__device__ __align__(16) __nv_bfloat16 g_xh[NROWS*Dn];       // scaled feats bf16  8MB
__device__ __align__(16) float g_proto[Bn*SLOT*Dn];          // fp32 proto accum  16MB
__device__ __align__(16) __nv_bfloat16 g_ph[Bn*SLOT*Dn];     // normed protos bf16 8MB
__device__ float g_logits[(size_t)Bn*Rn*SLOT];               // compacted logits  32MB
__device__ int   g_rslot[NROWS];                             // roi -> slot (-1 bg)
__device__ int   g_cnt[Bn*SLOT];                             // count per slot
__device__ int   g_nuniq[Bn];
__device__ float g_nll[NROWS];

// ---------------- helpers ----------------
__device__ __forceinline__ uint32_t smem_u32(const void* p) {
    uint32_t a;
    asm("{ .reg .u64 t; cvta.to.shared.u64 t, %1; cvt.u32.u64 %0, t; }" : "=r"(a) : "l"(p));
    return a;
}
__device__ __forceinline__ void ldm_x4(uint32_t* r, uint32_t addr) {
    asm volatile("ldmatrix.sync.aligned.m8n8.x4.shared.b16 {%0,%1,%2,%3}, [%4];"
        : "=r"(r[0]), "=r"(r[1]), "=r"(r[2]), "=r"(r[3]) : "r"(addr));
}
__device__ __forceinline__ void mma_bf16(float* c, const uint32_t* a, uint32_t b0, uint32_t b1) {
    asm volatile(
        "mma.sync.aligned.m16n8k16.row.col.f32.bf16.bf16.f32 "
        "{%0,%1,%2,%3}, {%4,%5,%6,%7}, {%8,%9}, {%0,%1,%2,%3};"
        : "+f"(c[0]), "+f"(c[1]), "+f"(c[2]), "+f"(c[3])
        : "r"(a[0]), "r"(a[1]), "r"(a[2]), "r"(a[3]), "r"(b0), "r"(b1));
}
__device__ __forceinline__ unsigned long long pack4bf(float a, float b, float c, float d) {
    __nv_bfloat162 lo = __floats2bfloat162_rn(a, b);
    __nv_bfloat162 hi = __floats2bfloat162_rn(c, d);
    unsigned int l = *reinterpret_cast<unsigned int*>(&lo);
    unsigned int h = *reinterpret_cast<unsigned int*>(&hi);
    return (unsigned long long)l | ((unsigned long long)h << 32);
}

// ---------------- 1: g_xh = bf16(inputs * cls) ; zero g_proto ----------------
__global__ void k_scale(const float* __restrict__ inp, const float* __restrict__ cls) {
    int i = blockIdx.x * 256 + threadIdx.x;      // float4 index; Dn/4=64 per row
    int row = i >> 6;
    float c = cls[row];
    float4 v = ((const float4*)inp)[i];
    ((unsigned long long*)g_xh)[i] = pack4bf(v.x * c, v.y * c, v.z * c, v.w * c);
    ((float4*)g_proto)[i] = make_float4(0.f, 0.f, 0.f, 0.f);   // Bn*SLOT*Dn/4 == NROWS*Dn/4
}

// ---------------- 2: per-image histogram + compaction -> rslot, counts ----------------
__global__ void k_compact(const int* __restrict__ roi_label) {
    int b = blockIdx.x;
    __shared__ int cnt[Pn];
    __shared__ int scan[257];
    for (int p = threadIdx.x; p < Pn; p += 256) cnt[p] = 0;
    __syncthreads();
    for (int r = threadIdx.x; r < Rn; r += 256) {
        int lab = roi_label[b*Rn + r] - 1;
        if (lab >= 0) atomicAdd(&cnt[lab], 1);
    }
    __syncthreads();
    const int chunk = (Pn + 255) / 256;   // 22
    int start = threadIdx.x * chunk;
    int local = 0;
    for (int i = 0; i < chunk; i++) {
        int p = start + i;
        if (p < Pn && cnt[p] > 0) local++;
    }
    scan[threadIdx.x + 1] = local;
    if (threadIdx.x == 0) scan[0] = 0;
    __syncthreads();
    if (threadIdx.x == 0) {
        for (int i = 1; i <= 256; i++) scan[i] += scan[i-1];
        g_nuniq[b] = scan[256];
    }
    __syncthreads();
    int off = scan[threadIdx.x];
    for (int i = 0; i < chunk; i++) {
        int p = start + i;
        if (p >= Pn) break;
        int c = cnt[p];
        if (c > 0) {
            g_cnt[b*SLOT + off] = c;
            cnt[p] = off;                 // overwrite count with slot id
            off++;
        } else {
            cnt[p] = -1;
        }
    }
    __syncthreads();
    for (int r = threadIdx.x; r < Rn; r += 256) {
        int lab = roi_label[b*Rn + r] - 1;
        g_rslot[b*Rn + r] = (lab >= 0) ? cnt[lab] : -1;
    }
}

// ---------------- 3: proto accumulate (one warp per roi, spread atomics) ----------------
__global__ void k_accum(const float* __restrict__ inp, const float* __restrict__ cls) {
    int row  = blockIdx.x * 8 + (threadIdx.x >> 5);
    int lane = threadIdx.x & 31;
    int js = g_rslot[row];
    if (js < 0) return;
    int b = row / Rn;
    float cc = cls[row];
    const float4* xr = (const float4*)(inp + (size_t)row * Dn);
    float* pr = g_proto + ((size_t)b*SLOT + js) * Dn;
    #pragma unroll
    for (int q = 0; q < 2; q++) {
        float4 v = xr[lane + q*32];
        float* d = pr + (lane + q*32) * 4;
        atomicAdd(d+0, v.x*cc);
        atomicAdd(d+1, v.y*cc);
        atomicAdd(d+2, v.z*cc);
        atomicAdd(d+3, v.w*cc);
    }
}

// ---------------- 4: proto normalize -> bf16 (one warp per slot) ----------------
__global__ void k_norm() {
    int idx  = blockIdx.x * 8 + (threadIdx.x >> 5);
    int lane = threadIdx.x & 31;
    int b = idx / SLOT, j = idx % SLOT;
    unsigned long long* dst = (unsigned long long*)(g_ph + (size_t)idx * Dn);
    if (j >= g_nuniq[b]) {
        dst[lane] = 0ull; dst[lane + 32] = 0ull;
        return;
    }
    const float* pr = g_proto + (size_t)idx * Dn;
    float4 v0 = ((const float4*)pr)[lane];
    float4 v1 = ((const float4*)pr)[lane + 32];
    float ss = v0.x*v0.x + v0.y*v0.y + v0.z*v0.z + v0.w*v0.w
             + v1.x*v1.x + v1.y*v1.y + v1.z*v1.z + v1.w*v1.w;
    #pragma unroll
    for (int o = 16; o > 0; o >>= 1) ss += __shfl_xor_sync(0xffffffffu, ss, o);
    float cf = (float)g_cnt[b*SLOT + j];
    float scale = 1.0f / (cf * fmaxf(sqrtf(ss) / cf, 1e-12f));
    dst[lane]      = pack4bf(v0.x*scale, v0.y*scale, v0.z*scale, v0.w*scale);
    dst[lane + 32] = pack4bf(v1.x*scale, v1.y*scale, v1.z*scale, v1.w*scale);
}

// ---------------- 5: bf16 mma.sync GEMM  C[128,128] tile per CTA ----------------
// 8 warps, each 64x32; K=256 in 4 chunks of 64, register-prefetch double buffer
__global__ __launch_bounds__(256, 2) void k_gemm_mma() {
    __shared__ __nv_bfloat16 sA[128*PAD];
    __shared__ __nv_bfloat16 sB[128*PAD];
    int tid = threadIdx.x;
    int warp = tid >> 5, lane = tid & 31;
    int b = blockIdx.z;
    int rBase = blockIdx.y * 128;
    int jBase = blockIdx.x * 128;
    const __nv_bfloat16* A  = g_xh + ((size_t)b*Rn   + rBase) * Dn;
    const __nv_bfloat16* Bp = g_ph + ((size_t)b*SLOT + jBase) * Dn;

    int wm = (warp >> 2) * 64;      // 0 / 64
    int wn = (warp & 3) * 32;       // 0 / 32 / 64 / 96

    float acc[4][4][4];
    #pragma unroll
    for (int mt = 0; mt < 4; mt++)
        #pragma unroll
        for (int nt = 0; nt < 4; nt++)
            #pragma unroll
            for (int q = 0; q < 4; q++) acc[mt][nt][q] = 0.f;

    uint32_t sAu = smem_u32(sA), sBu = smem_u32(sB);

    int aRow = (lane & 15);
    int aColOff = (lane >> 4) * 8;
    int bN = (lane & 7) + ((lane >> 4) << 3);
    int bKOff = ((lane >> 3) & 1) * 8;

    // per-thread gmem staging: 4 uint4 per array per chunk
    int srow = tid >> 1;                  // stage rows: each thread 2 cols x ... recompute below
    (void)srow;
    uint4 ra[4], rb[4];
    #pragma unroll
    for (int jj = 0; jj < 4; jj++) {
        int i = tid + jj*256;             // 0..1023
        int row = i >> 3, c = i & 7;
        ra[jj] = *(const uint4*)(A  + (size_t)row*Dn + c*8);
        rb[jj] = *(const uint4*)(Bp + (size_t)row*Dn + c*8);
    }

    for (int kc = 0; kc < 4; kc++) {
        if (kc) __syncthreads();          // previous compute done before overwrite
        #pragma unroll
        for (int jj = 0; jj < 4; jj++) {
            int i = tid + jj*256;
            int row = i >> 3, c = i & 7;
            *(uint4*)&sA[row*PAD + c*8] = ra[jj];
            *(uint4*)&sB[row*PAD + c*8] = rb[jj];
        }
        __syncthreads();
        if (kc < 3) {
            int k0 = (kc + 1) * 64;
            #pragma unroll
            for (int jj = 0; jj < 4; jj++) {
                int i = tid + jj*256;
                int row = i >> 3, c = i & 7;
                ra[jj] = *(const uint4*)(A  + (size_t)row*Dn + k0 + c*8);
                rb[jj] = *(const uint4*)(Bp + (size_t)row*Dn + k0 + c*8);
            }
        }
        #pragma unroll
        for (int ks = 0; ks < 4; ks++) {
            int kk = ks * 16;
            uint32_t a[4][4];
            #pragma unroll
            for (int mt = 0; mt < 4; mt++) {
                int row = wm + mt*16 + aRow;
                ldm_x4(a[mt], sAu + (row*PAD + kk + aColOff) * 2);
            }
            uint32_t bb[2][4];
            #pragma unroll
            for (int p = 0; p < 2; p++) {
                int n = wn + p*16 + bN;
                ldm_x4(bb[p], sBu + (n*PAD + kk + bKOff) * 2);
            }
            #pragma unroll
            for (int mt = 0; mt < 4; mt++)
                #pragma unroll
                for (int nt = 0; nt < 4; nt++)
                    mma_bf16(acc[mt][nt], a[mt],
                             bb[nt >> 1][(nt & 1)*2], bb[nt >> 1][(nt & 1)*2 + 1]);
        }
    }

    float* C = g_logits + ((size_t)b*Rn + rBase) * SLOT + jBase;
    int tg = lane >> 2, ti = lane & 3;
    #pragma unroll
    for (int mt = 0; mt < 4; mt++) {
        #pragma unroll
        for (int nt = 0; nt < 4; nt++) {
            int row0 = wm + mt*16 + tg;
            int col  = wn + nt*8 + ti*2;
            *(float2*)&C[(size_t)row0*SLOT + col]     = make_float2(acc[mt][nt][0], acc[mt][nt][1]);
            *(float2*)&C[(size_t)(row0+8)*SLOT + col] = make_float2(acc[mt][nt][2], acc[mt][nt][3]);
        }
    }
}

// ---------------- 6: online logsumexp + NLL (one warp per roi) ----------------
__global__ void k_nll() {
    int row  = blockIdx.x * 8 + (threadIdx.x >> 5);
    int lane = threadIdx.x & 31;
    int b = row / Rn, r = row % Rn;
    int jt = g_rslot[row];
    int nu = g_nuniq[b];
    const float* L = g_logits + ((size_t)b*Rn + r) * SLOT;

    float m = -3.0e38f, s = 0.f;
    for (int j = lane; j < nu; j += 32) {
        float l = L[j];
        float nm = fmaxf(m, l);
        s = s * __expf(m - nm) + __expf(l - nm);
        m = nm;
    }
    #pragma unroll
    for (int o = 16; o > 0; o >>= 1) {
        float om = __shfl_xor_sync(0xffffffffu, m, o);
        float os = __shfl_xor_sync(0xffffffffu, s, o);
        float nm = fmaxf(m, om);
        s = s * __expf(m - nm) + os * __expf(om - nm);
        m = nm;
    }
    if (lane == 0) {
        float out = 0.f;
        if (jt >= 0) out = (m + logf(s)) - L[jt];
        g_nll[row] = out;
    }
}

// ---------------- 7: final reduce ----------------
__global__ void k_reduce(const int* __restrict__ roi_label, float* __restrict__ out) {
    __shared__ float ssum[512];
    __shared__ int   scnt[512];
    float s = 0.f; int c = 0;
    for (int i = threadIdx.x; i < NROWS; i += 512) {
        s += g_nll[i];
        c += (roi_label[i] > 0);
    }
    ssum[threadIdx.x] = s; scnt[threadIdx.x] = c;
    __syncthreads();
    for (int o = 256; o > 0; o >>= 1) {
        if (threadIdx.x < o) {
            ssum[threadIdx.x] += ssum[threadIdx.x + o];
            scnt[threadIdx.x] += scnt[threadIdx.x + o];
        }
        __syncthreads();
    }
    if (threadIdx.x == 0)
        out[0] = ssum[0] / fmaxf((float)scnt[0], 1.0f);
}

extern "C" void kernel_launch(void* const* d_in, const int* in_sizes, int n_in,
                              void* d_out, int out_size) {
    const float* inp = (const float*)d_in[0];
    const float* cls = (const float*)d_in[1];
    const int*   lab = (const int*)d_in[2];
    float* out = (float*)d_out;

    k_scale<<<NROWS*Dn/4/256, 256>>>(inp, cls);
    k_compact<<<Bn, 256>>>(lab);
    k_accum<<<NROWS/8, 256>>>(inp, cls);
    k_norm<<<Bn*SLOT/8, 256>>>();
    k_gemm_mma<<<dim3(SLOT/128, Rn/128, Bn), 256>>>();
    k_nll<<<NROWS/8, 256>>>();
    k_reduce<<<1, 512>>>(lab, out);
}

// round 7
// speedup vs baseline: 2.5575x; 1.0005x over previous
#include <cuda_runtime.h>
#include <cuda_bf16.h>
#include <cstdint>
#include <math.h>

#define Bn 32
#define Rn 512
#define Dn 256
#define Pn 5532
#define SLOT 512
#define NROWS (Bn*Rn)
#define PAD 72                 // bf16 row stride in smem (64 + 8)

// ---------------- scratch ----------------
__device__ __align__(16) __nv_bfloat16 g_xh[NROWS*Dn];       // scaled feats bf16  8MB
__device__ __align__(16) float g_proto[Bn*SLOT*Dn];          // fp32 proto accum  16MB
__device__ __align__(16) __nv_bfloat16 g_ph[Bn*SLOT*Dn];     // normed protos bf16 8MB
__device__ __align__(16) float g_pm[NROWS*4];                // per-chunk row max
__device__ __align__(16) float g_ps[NROWS*4];                // per-chunk row sumexp
__device__ float g_tgt[NROWS];                               // target logit
__device__ int   g_rslot[NROWS];                             // roi -> slot (-1 bg)
__device__ int   g_cnt[Bn*SLOT];                             // count per slot
__device__ int   g_nuniq[Bn];

// ---------------- helpers ----------------
__device__ __forceinline__ uint32_t smem_u32(const void* p) {
    uint32_t a;
    asm("{ .reg .u64 t; cvta.to.shared.u64 t, %1; cvt.u32.u64 %0, t; }" : "=r"(a) : "l"(p));
    return a;
}
__device__ __forceinline__ void ldm_x4(uint32_t* r, uint32_t addr) {
    asm volatile("ldmatrix.sync.aligned.m8n8.x4.shared.b16 {%0,%1,%2,%3}, [%4];"
        : "=r"(r[0]), "=r"(r[1]), "=r"(r[2]), "=r"(r[3]) : "r"(addr));
}
__device__ __forceinline__ void mma_bf16(float* c, const uint32_t* a, uint32_t b0, uint32_t b1) {
    asm volatile(
        "mma.sync.aligned.m16n8k16.row.col.f32.bf16.bf16.f32 "
        "{%0,%1,%2,%3}, {%4,%5,%6,%7}, {%8,%9}, {%0,%1,%2,%3};"
        : "+f"(c[0]), "+f"(c[1]), "+f"(c[2]), "+f"(c[3])
        : "r"(a[0]), "r"(a[1]), "r"(a[2]), "r"(a[3]), "r"(b0), "r"(b1));
}
__device__ __forceinline__ unsigned long long pack4bf(float a, float b, float c, float d) {
    __nv_bfloat162 lo = __floats2bfloat162_rn(a, b);
    __nv_bfloat162 hi = __floats2bfloat162_rn(c, d);
    unsigned int l = *reinterpret_cast<unsigned int*>(&lo);
    unsigned int h = *reinterpret_cast<unsigned int*>(&hi);
    return (unsigned long long)l | ((unsigned long long)h << 32);
}

// ---------------- 1: g_xh = bf16(inputs * cls) ; zero g_proto ----------------
__global__ void k_scale(const float* __restrict__ inp, const float* __restrict__ cls) {
    int i = blockIdx.x * 256 + threadIdx.x;      // float4 index; Dn/4=64 per row
    int row = i >> 6;
    float c = cls[row];
    float4 v = ((const float4*)inp)[i];
    ((unsigned long long*)g_xh)[i] = pack4bf(v.x * c, v.y * c, v.z * c, v.w * c);
    ((float4*)g_proto)[i] = make_float4(0.f, 0.f, 0.f, 0.f);   // Bn*SLOT*Dn/4 == NROWS*Dn/4
}

// ---------------- 2: per-image histogram + compaction -> rslot, counts ----------------
__global__ void k_compact(const int* __restrict__ roi_label) {
    int b = blockIdx.x;
    __shared__ int cnt[Pn];
    __shared__ int scan[257];
    for (int p = threadIdx.x; p < Pn; p += 256) cnt[p] = 0;
    __syncthreads();
    for (int r = threadIdx.x; r < Rn; r += 256) {
        int lab = roi_label[b*Rn + r] - 1;
        if (lab >= 0) atomicAdd(&cnt[lab], 1);
    }
    __syncthreads();
    const int chunk = (Pn + 255) / 256;   // 22
    int start = threadIdx.x * chunk;
    int local = 0;
    for (int i = 0; i < chunk; i++) {
        int p = start + i;
        if (p < Pn && cnt[p] > 0) local++;
    }
    scan[threadIdx.x + 1] = local;
    if (threadIdx.x == 0) scan[0] = 0;
    __syncthreads();
    if (threadIdx.x == 0) {
        for (int i = 1; i <= 256; i++) scan[i] += scan[i-1];
        g_nuniq[b] = scan[256];
    }
    __syncthreads();
    int off = scan[threadIdx.x];
    for (int i = 0; i < chunk; i++) {
        int p = start + i;
        if (p >= Pn) break;
        int c = cnt[p];
        if (c > 0) {
            g_cnt[b*SLOT + off] = c;
            cnt[p] = off;                 // overwrite count with slot id
            off++;
        } else {
            cnt[p] = -1;
        }
    }
    __syncthreads();
    for (int r = threadIdx.x; r < Rn; r += 256) {
        int lab = roi_label[b*Rn + r] - 1;
        g_rslot[b*Rn + r] = (lab >= 0) ? cnt[lab] : -1;
    }
}

// ---------------- 3: proto accumulate (one warp per roi, spread atomics) ----------------
__global__ void k_accum(const float* __restrict__ inp, const float* __restrict__ cls) {
    int row  = blockIdx.x * 8 + (threadIdx.x >> 5);
    int lane = threadIdx.x & 31;
    int js = g_rslot[row];
    if (js < 0) return;
    int b = row / Rn;
    float cc = cls[row];
    const float4* xr = (const float4*)(inp + (size_t)row * Dn);
    float* pr = g_proto + ((size_t)b*SLOT + js) * Dn;
    #pragma unroll
    for (int q = 0; q < 2; q++) {
        float4 v = xr[lane + q*32];
        float* d = pr + (lane + q*32) * 4;
        atomicAdd(d+0, v.x*cc);
        atomicAdd(d+1, v.y*cc);
        atomicAdd(d+2, v.z*cc);
        atomicAdd(d+3, v.w*cc);
    }
}

// ---------------- 4: proto normalize -> bf16 (one warp per slot) ----------------
__global__ void k_norm() {
    int idx  = blockIdx.x * 8 + (threadIdx.x >> 5);
    int lane = threadIdx.x & 31;
    int b = idx / SLOT, j = idx % SLOT;
    unsigned long long* dst = (unsigned long long*)(g_ph + (size_t)idx * Dn);
    if (j >= g_nuniq[b]) {
        dst[lane] = 0ull; dst[lane + 32] = 0ull;
        return;
    }
    const float* pr = g_proto + (size_t)idx * Dn;
    float4 v0 = ((const float4*)pr)[lane];
    float4 v1 = ((const float4*)pr)[lane + 32];
    float ss = v0.x*v0.x + v0.y*v0.y + v0.z*v0.z + v0.w*v0.w
             + v1.x*v1.x + v1.y*v1.y + v1.z*v1.z + v1.w*v1.w;
    #pragma unroll
    for (int o = 16; o > 0; o >>= 1) ss += __shfl_xor_sync(0xffffffffu, ss, o);
    float cf = (float)g_cnt[b*SLOT + j];
    float scale = 1.0f / (cf * fmaxf(sqrtf(ss) / cf, 1e-12f));
    dst[lane]      = pack4bf(v0.x*scale, v0.y*scale, v0.z*scale, v0.w*scale);
    dst[lane + 32] = pack4bf(v1.x*scale, v1.y*scale, v1.z*scale, v1.w*scale);
}

// ---------------- 5: bf16 mma.sync GEMM + fused softmax partials ----------------
// C tile 128x128 per CTA; 8 warps 64x32; K=256 in 4 chunks, reg double-buffer.
// Epilogue: mask cols>=nu, per-row (max,sumexp) partial for this 128-col chunk,
// plus target-logit scatter. No logits array ever hits memory.
__global__ __launch_bounds__(256, 2) void k_gemm_mma() {
    __shared__ __nv_bfloat16 sA[128*PAD];
    __shared__ __nv_bfloat16 sB[128*PAD];
    __shared__ int   s_jt[128];
    __shared__ float s_m[4][128];
    __shared__ float s_s[4][128];
    int tid = threadIdx.x;
    int warp = tid >> 5, lane = tid & 31;
    int b = blockIdx.z;
    int rBase = blockIdx.y * 128;
    int jBase = blockIdx.x * 128;
    const __nv_bfloat16* A  = g_xh + ((size_t)b*Rn   + rBase) * Dn;
    const __nv_bfloat16* Bp = g_ph + ((size_t)b*SLOT + jBase) * Dn;

    if (tid < 128) s_jt[tid] = g_rslot[b*Rn + rBase + tid];

    int wm = (warp >> 2) * 64;      // 0 / 64
    int wn = (warp & 3) * 32;       // 0 / 32 / 64 / 96
    int wq = warp & 3;

    float acc[4][4][4];
    #pragma unroll
    for (int mt = 0; mt < 4; mt++)
        #pragma unroll
        for (int nt = 0; nt < 4; nt++)
            #pragma unroll
            for (int q = 0; q < 4; q++) acc[mt][nt][q] = 0.f;

    uint32_t sAu = smem_u32(sA), sBu = smem_u32(sB);

    int aRow = (lane & 15);
    int aColOff = (lane >> 4) * 8;
    int bN = (lane & 7) + ((lane >> 4) << 3);
    int bKOff = ((lane >> 3) & 1) * 8;

    uint4 ra[4], rb[4];
    #pragma unroll
    for (int jj = 0; jj < 4; jj++) {
        int i = tid + jj*256;             // 0..1023
        int row = i >> 3, c = i & 7;
        ra[jj] = *(const uint4*)(A  + (size_t)row*Dn + c*8);
        rb[jj] = *(const uint4*)(Bp + (size_t)row*Dn + c*8);
    }

    for (int kc = 0; kc < 4; kc++) {
        if (kc) __syncthreads();
        #pragma unroll
        for (int jj = 0; jj < 4; jj++) {
            int i = tid + jj*256;
            int row = i >> 3, c = i & 7;
            *(uint4*)&sA[row*PAD + c*8] = ra[jj];
            *(uint4*)&sB[row*PAD + c*8] = rb[jj];
        }
        __syncthreads();
        if (kc < 3) {
            int k0 = (kc + 1) * 64;
            #pragma unroll
            for (int jj = 0; jj < 4; jj++) {
                int i = tid + jj*256;
                int row = i >> 3, c = i & 7;
                ra[jj] = *(const uint4*)(A  + (size_t)row*Dn + k0 + c*8);
                rb[jj] = *(const uint4*)(Bp + (size_t)row*Dn + k0 + c*8);
            }
        }
        #pragma unroll
        for (int ks = 0; ks < 4; ks++) {
            int kk = ks * 16;
            uint32_t a[4][4];
            #pragma unroll
            for (int mt = 0; mt < 4; mt++) {
                int row = wm + mt*16 + aRow;
                ldm_x4(a[mt], sAu + (row*PAD + kk + aColOff) * 2);
            }
            uint32_t bb[2][4];
            #pragma unroll
            for (int p = 0; p < 2; p++) {
                int n = wn + p*16 + bN;
                ldm_x4(bb[p], sBu + (n*PAD + kk + bKOff) * 2);
            }
            #pragma unroll
            for (int mt = 0; mt < 4; mt++)
                #pragma unroll
                for (int nt = 0; nt < 4; nt++)
                    mma_bf16(acc[mt][nt], a[mt],
                             bb[nt >> 1][(nt & 1)*2], bb[nt >> 1][(nt & 1)*2 + 1]);
        }
    }

    // ---- fused epilogue: per-row partial (max, sumexp) over this 128-col chunk ----
    int nu = g_nuniq[b];
    int tg = lane >> 2, ti = lane & 3;
    #pragma unroll
    for (int mt = 0; mt < 4; mt++) {
        #pragma unroll
        for (int h = 0; h < 2; h++) {
            int rowL = wm + mt*16 + tg + h*8;
            int jt = s_jt[rowL];
            float vals[8];
            float vmax = -1e30f;
            #pragma unroll
            for (int nt = 0; nt < 4; nt++) {
                #pragma unroll
                for (int ql = 0; ql < 2; ql++) {
                    int j = jBase + wn + nt*8 + ti*2 + ql;
                    float v = acc[mt][nt][h*2 + ql];
                    if (j == jt) g_tgt[b*Rn + rBase + rowL] = v;
                    float vv = (j < nu) ? v : -1e30f;
                    vals[nt*2 + ql] = vv;
                    vmax = fmaxf(vmax, vv);
                }
            }
            vmax = fmaxf(vmax, __shfl_xor_sync(0xffffffffu, vmax, 1));
            vmax = fmaxf(vmax, __shfl_xor_sync(0xffffffffu, vmax, 2));
            float se = 0.f;
            #pragma unroll
            for (int q = 0; q < 8; q++) se += __expf(vals[q] - vmax);
            se += __shfl_xor_sync(0xffffffffu, se, 1);
            se += __shfl_xor_sync(0xffffffffu, se, 2);
            if (ti == 0) { s_m[wq][rowL] = vmax; s_s[wq][rowL] = se; }
        }
    }
    __syncthreads();
    if (tid < 128) {
        float m0 = s_m[0][tid], m1 = s_m[1][tid], m2 = s_m[2][tid], m3 = s_m[3][tid];
        float m = fmaxf(fmaxf(m0, m1), fmaxf(m2, m3));
        float s = s_s[0][tid]*__expf(m0 - m) + s_s[1][tid]*__expf(m1 - m)
                + s_s[2][tid]*__expf(m2 - m) + s_s[3][tid]*__expf(m3 - m);
        int roi = b*Rn + rBase + tid;
        g_pm[roi*4 + blockIdx.x] = m;
        g_ps[roi*4 + blockIdx.x] = s;
    }
}

// ---------------- 6: combine partials + NLL + mean (single block) ----------------
__global__ void k_final(float* __restrict__ out) {
    __shared__ float ssum[512];
    __shared__ int   scnt[512];
    float sum = 0.f; int cnt = 0;
    for (int i = threadIdx.x; i < NROWS; i += 512) {
        int jt = g_rslot[i];
        if (jt >= 0) {
            float4 pm = *(const float4*)&g_pm[i*4];
            float4 ps = *(const float4*)&g_ps[i*4];
            float m = fmaxf(fmaxf(pm.x, pm.y), fmaxf(pm.z, pm.w));
            float s = ps.x*__expf(pm.x - m) + ps.y*__expf(pm.y - m)
                    + ps.z*__expf(pm.z - m) + ps.w*__expf(pm.w - m);
            sum += (m + logf(s)) - g_tgt[i];
            cnt++;
        }
    }
    ssum[threadIdx.x] = sum; scnt[threadIdx.x] = cnt;
    __syncthreads();
    for (int o = 256; o > 0; o >>= 1) {
        if (threadIdx.x < o) {
            ssum[threadIdx.x] += ssum[threadIdx.x + o];
            scnt[threadIdx.x] += scnt[threadIdx.x + o];
        }
        __syncthreads();
    }
    if (threadIdx.x == 0)
        out[0] = ssum[0] / fmaxf((float)scnt[0], 1.0f);
}

extern "C" void kernel_launch(void* const* d_in, const int* in_sizes, int n_in,
                              void* d_out, int out_size) {
    const float* inp = (const float*)d_in[0];
    const float* cls = (const float*)d_in[1];
    const int*   lab = (const int*)d_in[2];
    float* out = (float*)d_out;

    k_scale<<<NROWS*Dn/4/256, 256>>>(inp, cls);
    k_compact<<<Bn, 256>>>(lab);
    k_accum<<<NROWS/8, 256>>>(inp, cls);
    k_norm<<<Bn*SLOT/8, 256>>>();
    k_gemm_mma<<<dim3(SLOT/128, Rn/128, Bn), 256>>>();
    k_final<<<1, 512>>>(out);
}

// round 8
// speedup vs baseline: 2.6634x; 1.0414x over previous
#include <cuda_runtime.h>
#include <cuda_bf16.h>
#include <cstdint>
#include <math.h>

#define Bn 32
#define Rn 512
#define Dn 256
#define Pn 5532
#define SLOT 512
#define NROWS (Bn*Rn)
#define PAD 72                 // bf16 row stride in smem (64 + 8)
#define STAGE_ELE (128*PAD)    // elements per tile per stage

// ---------------- scratch ----------------
__device__ __align__(16) __nv_bfloat16 g_xh[NROWS*Dn];       // scaled feats bf16  8MB
__device__ __align__(16) float g_proto[Bn*SLOT*Dn];          // fp32 proto accum  16MB
__device__ __align__(16) __nv_bfloat16 g_ph[Bn*SLOT*Dn];     // normed protos bf16 8MB
__device__ __align__(16) float g_pm[NROWS*4];                // per-chunk row max
__device__ __align__(16) float g_ps[NROWS*4];                // per-chunk row sumexp
__device__ float g_tgt[NROWS];                               // target logit
__device__ int   g_rslot[NROWS];                             // roi -> slot (-1 bg)
__device__ int   g_cnt[Bn*SLOT];                             // count per slot
__device__ int   g_nuniq[Bn];

// ---------------- helpers ----------------
__device__ __forceinline__ uint32_t smem_u32(const void* p) {
    uint32_t a;
    asm("{ .reg .u64 t; cvta.to.shared.u64 t, %1; cvt.u32.u64 %0, t; }" : "=r"(a) : "l"(p));
    return a;
}
__device__ __forceinline__ void cp16(uint32_t dst, const void* src) {
    asm volatile("cp.async.cg.shared.global [%0], [%1], 16;" :: "r"(dst), "l"(src));
}
__device__ __forceinline__ void cp_commit() {
    asm volatile("cp.async.commit_group;" ::: "memory");
}
template<int N> __device__ __forceinline__ void cp_wait() {
    asm volatile("cp.async.wait_group %0;" :: "n"(N) : "memory");
}
__device__ __forceinline__ void ldm_x4(uint32_t* r, uint32_t addr) {
    asm volatile("ldmatrix.sync.aligned.m8n8.x4.shared.b16 {%0,%1,%2,%3}, [%4];"
        : "=r"(r[0]), "=r"(r[1]), "=r"(r[2]), "=r"(r[3]) : "r"(addr));
}
__device__ __forceinline__ void mma_bf16(float* c, const uint32_t* a, uint32_t b0, uint32_t b1) {
    asm volatile(
        "mma.sync.aligned.m16n8k16.row.col.f32.bf16.bf16.f32 "
        "{%0,%1,%2,%3}, {%4,%5,%6,%7}, {%8,%9}, {%0,%1,%2,%3};"
        : "+f"(c[0]), "+f"(c[1]), "+f"(c[2]), "+f"(c[3])
        : "r"(a[0]), "r"(a[1]), "r"(a[2]), "r"(a[3]), "r"(b0), "r"(b1));
}
__device__ __forceinline__ unsigned long long pack4bf(float a, float b, float c, float d) {
    __nv_bfloat162 lo = __floats2bfloat162_rn(a, b);
    __nv_bfloat162 hi = __floats2bfloat162_rn(c, d);
    unsigned int l = *reinterpret_cast<unsigned int*>(&lo);
    unsigned int h = *reinterpret_cast<unsigned int*>(&hi);
    return (unsigned long long)l | ((unsigned long long)h << 32);
}

// ---------------- 1: histogram+compaction (blocks 0..31) ; zero g_proto (rest) ----------
__global__ void k_compact(const int* __restrict__ roi_label) {
    if (blockIdx.x >= Bn) {                       // zeroing blocks
        int zb = blockIdx.x - Bn;                 // 0..2047
        float4* p = (float4*)g_proto;
        p[zb*512 + threadIdx.x]       = make_float4(0.f,0.f,0.f,0.f);
        p[zb*512 + 256 + threadIdx.x] = make_float4(0.f,0.f,0.f,0.f);
        return;
    }
    int b = blockIdx.x;
    __shared__ int cnt[Pn];
    __shared__ int scan[257];
    for (int p = threadIdx.x; p < Pn; p += 256) cnt[p] = 0;
    __syncthreads();
    for (int r = threadIdx.x; r < Rn; r += 256) {
        int lab = roi_label[b*Rn + r] - 1;
        if (lab >= 0) atomicAdd(&cnt[lab], 1);
    }
    __syncthreads();
    const int chunk = (Pn + 255) / 256;   // 22
    int start = threadIdx.x * chunk;
    int local = 0;
    for (int i = 0; i < chunk; i++) {
        int p = start + i;
        if (p < Pn && cnt[p] > 0) local++;
    }
    scan[threadIdx.x + 1] = local;
    if (threadIdx.x == 0) scan[0] = 0;
    __syncthreads();
    if (threadIdx.x == 0) {
        for (int i = 1; i <= 256; i++) scan[i] += scan[i-1];
        g_nuniq[b] = scan[256];
    }
    __syncthreads();
    int off = scan[threadIdx.x];
    for (int i = 0; i < chunk; i++) {
        int p = start + i;
        if (p >= Pn) break;
        int c = cnt[p];
        if (c > 0) {
            g_cnt[b*SLOT + off] = c;
            cnt[p] = off;                 // overwrite count with slot id
            off++;
        } else {
            cnt[p] = -1;
        }
    }
    __syncthreads();
    for (int r = threadIdx.x; r < Rn; r += 256) {
        int lab = roi_label[b*Rn + r] - 1;
        g_rslot[b*Rn + r] = (lab >= 0) ? cnt[lab] : -1;
    }
}

// ---------------- 2: fused scale->bf16 + proto atomic accumulate (warp per roi) ------
__global__ void k_prep(const float* __restrict__ inp, const float* __restrict__ cls) {
    int row  = blockIdx.x * 8 + (threadIdx.x >> 5);
    int lane = threadIdx.x & 31;
    int b = row / Rn;
    int js = g_rslot[row];
    float cc = cls[row];
    const float4* xr = (const float4*)(inp + (size_t)row * Dn);
    unsigned long long* xh = (unsigned long long*)(g_xh + (size_t)row * Dn);
    float* pr = (js >= 0) ? (g_proto + ((size_t)b*SLOT + js) * Dn) : nullptr;
    #pragma unroll
    for (int q = 0; q < 2; q++) {
        int c = lane + q*32;
        float4 v = xr[c];
        v.x *= cc; v.y *= cc; v.z *= cc; v.w *= cc;
        xh[c] = pack4bf(v.x, v.y, v.z, v.w);
        if (pr) {
            float* d = pr + c*4;
            atomicAdd(d+0, v.x);
            atomicAdd(d+1, v.y);
            atomicAdd(d+2, v.z);
            atomicAdd(d+3, v.w);
        }
    }
}

// ---------------- 3: proto normalize -> bf16 (one warp per slot) ----------------
__global__ void k_norm() {
    int idx  = blockIdx.x * 8 + (threadIdx.x >> 5);
    int lane = threadIdx.x & 31;
    int b = idx / SLOT, j = idx % SLOT;
    unsigned long long* dst = (unsigned long long*)(g_ph + (size_t)idx * Dn);
    if (j >= g_nuniq[b]) {
        dst[lane] = 0ull; dst[lane + 32] = 0ull;
        return;
    }
    const float* pr = g_proto + (size_t)idx * Dn;
    float4 v0 = ((const float4*)pr)[lane];
    float4 v1 = ((const float4*)pr)[lane + 32];
    float ss = v0.x*v0.x + v0.y*v0.y + v0.z*v0.z + v0.w*v0.w
             + v1.x*v1.x + v1.y*v1.y + v1.z*v1.z + v1.w*v1.w;
    #pragma unroll
    for (int o = 16; o > 0; o >>= 1) ss += __shfl_xor_sync(0xffffffffu, ss, o);
    float cf = (float)g_cnt[b*SLOT + j];
    float scale = 1.0f / (cf * fmaxf(sqrtf(ss) / cf, 1e-12f));
    dst[lane]      = pack4bf(v0.x*scale, v0.y*scale, v0.z*scale, v0.w*scale);
    dst[lane + 32] = pack4bf(v1.x*scale, v1.y*scale, v1.z*scale, v1.w*scale);
}

// ---------------- 4: bf16 mma.sync GEMM (cp.async 2-stage) + fused softmax partials --
__global__ __launch_bounds__(256, 2) void k_gemm_mma() {
    extern __shared__ __nv_bfloat16 smem[];      // [2][sA 128*PAD | sB 128*PAD]
    __shared__ int   s_jt[128];
    __shared__ float s_m[4][128];
    __shared__ float s_s[4][128];
    int tid = threadIdx.x;
    int warp = tid >> 5, lane = tid & 31;
    int b = blockIdx.z;
    int rBase = blockIdx.y * 128;
    int jBase = blockIdx.x * 128;
    const __nv_bfloat16* A  = g_xh + ((size_t)b*Rn   + rBase) * Dn;
    const __nv_bfloat16* Bp = g_ph + ((size_t)b*SLOT + jBase) * Dn;

    if (tid < 128) s_jt[tid] = g_rslot[b*Rn + rBase + tid];

    int wm = (warp >> 2) * 64;      // 0 / 64
    int wn = (warp & 3) * 32;       // 0 / 32 / 64 / 96
    int wq = warp & 3;

    float acc[4][4][4];
    #pragma unroll
    for (int mt = 0; mt < 4; mt++)
        #pragma unroll
        for (int nt = 0; nt < 4; nt++)
            #pragma unroll
            for (int q = 0; q < 4; q++) acc[mt][nt][q] = 0.f;

    uint32_t sBase = smem_u32(smem);
    // per-stage byte offsets
    const uint32_t stageBytes = 2u * STAGE_ELE * 2u;  // A+B per stage
    const uint32_t sBoff = STAGE_ELE * 2u;

    int aRow = (lane & 15);
    int aColOff = (lane >> 4) * 8;
    int bN = (lane & 7) + ((lane >> 4) << 3);
    int bKOff = ((lane >> 3) & 1) * 8;

    // staging: each thread 4 (row,c) pairs per array
    int srow[4], scol[4];
    #pragma unroll
    for (int jj = 0; jj < 4; jj++) {
        int i = tid + jj*256;
        srow[jj] = i >> 3; scol[jj] = i & 7;
    }

    // issue stage for chunk kc into buffer stg
    #define ISSUE(kc, stg) { \
        uint32_t d0 = sBase + (stg)*stageBytes; \
        _Pragma("unroll") \
        for (int jj = 0; jj < 4; jj++) { \
            uint32_t off = (srow[jj]*PAD + scol[jj]*8) * 2; \
            cp16(d0 + off,          A  + (size_t)srow[jj]*Dn + (kc)*64 + scol[jj]*8); \
            cp16(d0 + sBoff + off,  Bp + (size_t)srow[jj]*Dn + (kc)*64 + scol[jj]*8); \
        } \
        cp_commit(); \
    }

    ISSUE(0, 0);
    for (int kc = 0; kc < 4; kc++) {
        if (kc) __syncthreads();               // all done computing stage (kc-1)&1
        if (kc < 3) ISSUE(kc + 1, (kc + 1) & 1);
        if (kc < 3) cp_wait<1>(); else cp_wait<0>();
        __syncthreads();
        uint32_t sAu = sBase + (kc & 1)*stageBytes;
        uint32_t sBu = sAu + sBoff;
        #pragma unroll
        for (int ks = 0; ks < 4; ks++) {
            int kk = ks * 16;
            uint32_t a[4][4];
            #pragma unroll
            for (int mt = 0; mt < 4; mt++) {
                int row = wm + mt*16 + aRow;
                ldm_x4(a[mt], sAu + (row*PAD + kk + aColOff) * 2);
            }
            uint32_t bb[2][4];
            #pragma unroll
            for (int p = 0; p < 2; p++) {
                int n = wn + p*16 + bN;
                ldm_x4(bb[p], sBu + (n*PAD + kk + bKOff) * 2);
            }
            #pragma unroll
            for (int mt = 0; mt < 4; mt++)
                #pragma unroll
                for (int nt = 0; nt < 4; nt++)
                    mma_bf16(acc[mt][nt], a[mt],
                             bb[nt >> 1][(nt & 1)*2], bb[nt >> 1][(nt & 1)*2 + 1]);
        }
    }

    // ---- fused epilogue: per-row partial (max, sumexp) over this 128-col chunk ----
    int nu = g_nuniq[b];
    int tg = lane >> 2, ti = lane & 3;
    #pragma unroll
    for (int mt = 0; mt < 4; mt++) {
        #pragma unroll
        for (int h = 0; h < 2; h++) {
            int rowL = wm + mt*16 + tg + h*8;
            int jt = s_jt[rowL];
            float vals[8];
            float vmax = -1e30f;
            #pragma unroll
            for (int nt = 0; nt < 4; nt++) {
                #pragma unroll
                for (int ql = 0; ql < 2; ql++) {
                    int j = jBase + wn + nt*8 + ti*2 + ql;
                    float v = acc[mt][nt][h*2 + ql];
                    if (j == jt) g_tgt[b*Rn + rBase + rowL] = v;
                    float vv = (j < nu) ? v : -1e30f;
                    vals[nt*2 + ql] = vv;
                    vmax = fmaxf(vmax, vv);
                }
            }
            vmax = fmaxf(vmax, __shfl_xor_sync(0xffffffffu, vmax, 1));
            vmax = fmaxf(vmax, __shfl_xor_sync(0xffffffffu, vmax, 2));
            float se = 0.f;
            #pragma unroll
            for (int q = 0; q < 8; q++) se += __expf(vals[q] - vmax);
            se += __shfl_xor_sync(0xffffffffu, se, 1);
            se += __shfl_xor_sync(0xffffffffu, se, 2);
            if (ti == 0) { s_m[wq][rowL] = vmax; s_s[wq][rowL] = se; }
        }
    }
    __syncthreads();
    if (tid < 128) {
        float m0 = s_m[0][tid], m1 = s_m[1][tid], m2 = s_m[2][tid], m3 = s_m[3][tid];
        float m = fmaxf(fmaxf(m0, m1), fmaxf(m2, m3));
        float s = s_s[0][tid]*__expf(m0 - m) + s_s[1][tid]*__expf(m1 - m)
                + s_s[2][tid]*__expf(m2 - m) + s_s[3][tid]*__expf(m3 - m);
        int roi = b*Rn + rBase + tid;
        g_pm[roi*4 + blockIdx.x] = m;
        g_ps[roi*4 + blockIdx.x] = s;
    }
}

// ---------------- 5: combine partials + NLL + mean (single block) ----------------
__global__ void k_final(float* __restrict__ out) {
    __shared__ float ssum[512];
    __shared__ int   scnt[512];
    float sum = 0.f; int cnt = 0;
    for (int i = threadIdx.x; i < NROWS; i += 512) {
        int jt = g_rslot[i];
        if (jt >= 0) {
            float4 pm = *(const float4*)&g_pm[i*4];
            float4 ps = *(const float4*)&g_ps[i*4];
            float m = fmaxf(fmaxf(pm.x, pm.y), fmaxf(pm.z, pm.w));
            float s = ps.x*__expf(pm.x - m) + ps.y*__expf(pm.y - m)
                    + ps.z*__expf(pm.z - m) + ps.w*__expf(pm.w - m);
            sum += (m + logf(s)) - g_tgt[i];
            cnt++;
        }
    }
    ssum[threadIdx.x] = sum; scnt[threadIdx.x] = cnt;
    __syncthreads();
    for (int o = 256; o > 0; o >>= 1) {
        if (threadIdx.x < o) {
            ssum[threadIdx.x] += ssum[threadIdx.x + o];
            scnt[threadIdx.x] += scnt[threadIdx.x + o];
        }
        __syncthreads();
    }
    if (threadIdx.x == 0)
        out[0] = ssum[0] / fmaxf((float)scnt[0], 1.0f);
}

extern "C" void kernel_launch(void* const* d_in, const int* in_sizes, int n_in,
                              void* d_out, int out_size) {
    const float* inp = (const float*)d_in[0];
    const float* cls = (const float*)d_in[1];
    const int*   lab = (const int*)d_in[2];
    float* out = (float*)d_out;

    const int gemmSmem = 2 * 2 * STAGE_ELE * 2;  // 2 stages x (A+B) x bytes = 73728
    cudaFuncSetAttribute(k_gemm_mma, cudaFuncAttributeMaxDynamicSharedMemorySize, gemmSmem);

    k_compact<<<Bn + 2048, 256>>>(lab);
    k_prep<<<NROWS/8, 256>>>(inp, cls);
    k_norm<<<Bn*SLOT/8, 256>>>();
    k_gemm_mma<<<dim3(SLOT/128, Rn/128, Bn), 256, gemmSmem>>>();
    k_final<<<1, 512>>>(out);
}

// round 9
// speedup vs baseline: 2.7034x; 1.0150x over previous
#include <cuda_runtime.h>
#include <cuda_bf16.h>
#include <cstdint>
#include <math.h>

#define Bn 32
#define Rn 512
#define Dn 256
#define Pn 5532
#define SLOT 512
#define NROWS (Bn*Rn)
#define PAD 72                 // bf16 row stride in smem (64 + 8)
#define STAGE_ELE (128*PAD)    // elements per tile per stage

// ---------------- scratch ----------------
__device__ __align__(16) __nv_bfloat16 g_xh[NROWS*Dn];       // scaled feats bf16  8MB
__device__ __align__(16) __nv_bfloat16 g_ph[Bn*SLOT*Dn];     // normed protos bf16 8MB
__device__ __align__(16) float g_pm[NROWS*4];                // per-chunk row max
__device__ __align__(16) float g_ps[NROWS*4];                // per-chunk row sumexp
__device__ float g_tgt[NROWS];                               // target logit
__device__ int   g_rslot[NROWS];                             // roi -> slot (-1 bg)
__device__ int   g_sorted[NROWS];                            // rois sorted by slot (per image)
__device__ int   g_cnt[Bn*SLOT];                             // count per slot
__device__ int   g_cstart[Bn*SLOT];                          // member start per slot
__device__ int   g_nuniq[Bn];

// ---------------- helpers ----------------
__device__ __forceinline__ uint32_t smem_u32(const void* p) {
    uint32_t a;
    asm("{ .reg .u64 t; cvta.to.shared.u64 t, %1; cvt.u32.u64 %0, t; }" : "=r"(a) : "l"(p));
    return a;
}
__device__ __forceinline__ void cp16(uint32_t dst, const void* src) {
    asm volatile("cp.async.cg.shared.global [%0], [%1], 16;" :: "r"(dst), "l"(src));
}
__device__ __forceinline__ void cp_commit() {
    asm volatile("cp.async.commit_group;" ::: "memory");
}
template<int N> __device__ __forceinline__ void cp_wait() {
    asm volatile("cp.async.wait_group %0;" :: "n"(N) : "memory");
}
__device__ __forceinline__ void ldm_x4(uint32_t* r, uint32_t addr) {
    asm volatile("ldmatrix.sync.aligned.m8n8.x4.shared.b16 {%0,%1,%2,%3}, [%4];"
        : "=r"(r[0]), "=r"(r[1]), "=r"(r[2]), "=r"(r[3]) : "r"(addr));
}
__device__ __forceinline__ void mma_bf16(float* c, const uint32_t* a, uint32_t b0, uint32_t b1) {
    asm volatile(
        "mma.sync.aligned.m16n8k16.row.col.f32.bf16.bf16.f32 "
        "{%0,%1,%2,%3}, {%4,%5,%6,%7}, {%8,%9}, {%0,%1,%2,%3};"
        : "+f"(c[0]), "+f"(c[1]), "+f"(c[2]), "+f"(c[3])
        : "r"(a[0]), "r"(a[1]), "r"(a[2]), "r"(a[3]), "r"(b0), "r"(b1));
}
__device__ __forceinline__ unsigned long long pack4bf(float a, float b, float c, float d) {
    __nv_bfloat162 lo = __floats2bfloat162_rn(a, b);
    __nv_bfloat162 hi = __floats2bfloat162_rn(c, d);
    unsigned int l = *reinterpret_cast<unsigned int*>(&lo);
    unsigned int h = *reinterpret_cast<unsigned int*>(&hi);
    return (unsigned long long)l | ((unsigned long long)h << 32);
}

// ---------------- 1: pure scale  g_xh = bf16(inputs * cls) ----------------
__global__ void k_prep(const float* __restrict__ inp, const float* __restrict__ cls) {
    int i = blockIdx.x * 256 + threadIdx.x;      // float4 index; Dn/4=64 per row
    int row = i >> 6;
    float c = cls[row];
    float4 v = ((const float4*)inp)[i];
    ((unsigned long long*)g_xh)[i] = pack4bf(v.x * c, v.y * c, v.z * c, v.w * c);
}

// ---------------- 2: histogram + compaction + counting sort ----------------
__global__ void k_compact(const int* __restrict__ roi_label) {
    int b = blockIdx.x;
    __shared__ int cnt[Pn];          // counts, then pid -> slot id
    __shared__ int scanU[257];       // unique scan
    __shared__ int scanC[257];       // count scan
    __shared__ int s_cur[SLOT];      // per-slot write cursor
    for (int p = threadIdx.x; p < Pn; p += 256) cnt[p] = 0;
    __syncthreads();
    for (int r = threadIdx.x; r < Rn; r += 256) {
        int lab = roi_label[b*Rn + r] - 1;
        if (lab >= 0) atomicAdd(&cnt[lab], 1);
    }
    __syncthreads();
    const int chunk = (Pn + 255) / 256;   // 22
    int start = threadIdx.x * chunk;
    int lu = 0, lc = 0;
    for (int i = 0; i < chunk; i++) {
        int p = start + i;
        if (p < Pn) { int c = cnt[p]; if (c > 0) { lu++; lc += c; } }
    }
    scanU[threadIdx.x + 1] = lu;
    scanC[threadIdx.x + 1] = lc;
    if (threadIdx.x == 0) { scanU[0] = 0; scanC[0] = 0; }
    __syncthreads();
    if (threadIdx.x == 0) {
        for (int i = 1; i <= 256; i++) { scanU[i] += scanU[i-1]; scanC[i] += scanC[i-1]; }
        g_nuniq[b] = scanU[256];
    }
    __syncthreads();
    int off = scanU[threadIdx.x];
    int cst = scanC[threadIdx.x];
    for (int i = 0; i < chunk; i++) {
        int p = start + i;
        if (p >= Pn) break;
        int c = cnt[p];
        if (c > 0) {
            g_cnt[b*SLOT + off]    = c;
            g_cstart[b*SLOT + off] = cst;
            s_cur[off] = cst;
            cnt[p] = off;
            off++; cst += c;
        } else {
            cnt[p] = -1;
        }
    }
    __syncthreads();
    for (int r = threadIdx.x; r < Rn; r += 256) {
        int lab = roi_label[b*Rn + r] - 1;
        int slot = (lab >= 0) ? cnt[lab] : -1;
        g_rslot[b*Rn + r] = slot;
        if (slot >= 0) {
            int pos = atomicAdd(&s_cur[slot], 1);
            g_sorted[b*Rn + pos] = r;
        }
    }
}

// ---------------- 3: proto gather + normalize -> bf16 (one warp per slot) ----------------
__global__ void k_norm() {
    int idx  = blockIdx.x * 8 + (threadIdx.x >> 5);
    int lane = threadIdx.x & 31;
    int b = idx / SLOT, j = idx % SLOT;
    uint4* dst = (uint4*)(g_ph + (size_t)idx * Dn);   // 32 lanes x 16B = 512B row
    if (j >= g_nuniq[b]) {
        dst[lane] = make_uint4(0, 0, 0, 0);
        return;
    }
    int c  = g_cnt[b*SLOT + j];
    int st = g_cstart[b*SLOT + j];
    float acc[8];
    #pragma unroll
    for (int q = 0; q < 8; q++) acc[q] = 0.f;
    for (int m = 0; m < c; m++) {
        int r = g_sorted[b*Rn + st + m];
        uint4 v = ((const uint4*)(g_xh + (size_t)(b*Rn + r) * Dn))[lane];
        uint32_t w[4] = {v.x, v.y, v.z, v.w};
        #pragma unroll
        for (int q = 0; q < 4; q++) {
            float2 f = __bfloat1622float2(*(__nv_bfloat162*)&w[q]);
            acc[q*2]   += f.x;
            acc[q*2+1] += f.y;
        }
    }
    float ss = 0.f;
    #pragma unroll
    for (int q = 0; q < 8; q++) ss += acc[q]*acc[q];
    #pragma unroll
    for (int o = 16; o > 0; o >>= 1) ss += __shfl_xor_sync(0xffffffffu, ss, o);
    float cf = (float)c;
    float scale = 1.0f / (cf * fmaxf(sqrtf(ss) / cf, 1e-12f));
    uint32_t o0, o1, o2, o3;
    {
        __nv_bfloat162 p0 = __floats2bfloat162_rn(acc[0]*scale, acc[1]*scale);
        __nv_bfloat162 p1 = __floats2bfloat162_rn(acc[2]*scale, acc[3]*scale);
        __nv_bfloat162 p2 = __floats2bfloat162_rn(acc[4]*scale, acc[5]*scale);
        __nv_bfloat162 p3 = __floats2bfloat162_rn(acc[6]*scale, acc[7]*scale);
        o0 = *(uint32_t*)&p0; o1 = *(uint32_t*)&p1; o2 = *(uint32_t*)&p2; o3 = *(uint32_t*)&p3;
    }
    dst[lane] = make_uint4(o0, o1, o2, o3);
}

// ---------------- 4: bf16 mma.sync GEMM (cp.async 2-stage) + fused softmax partials --
__global__ __launch_bounds__(256, 2) void k_gemm_mma() {
    extern __shared__ __nv_bfloat16 smem[];      // [2][sA 128*PAD | sB 128*PAD]
    __shared__ int   s_jt[128];
    __shared__ float s_m[4][128];
    __shared__ float s_s[4][128];
    int tid = threadIdx.x;
    int warp = tid >> 5, lane = tid & 31;
    int b = blockIdx.z;
    int rBase = blockIdx.y * 128;
    int jBase = blockIdx.x * 128;
    const __nv_bfloat16* A  = g_xh + ((size_t)b*Rn   + rBase) * Dn;
    const __nv_bfloat16* Bp = g_ph + ((size_t)b*SLOT + jBase) * Dn;

    if (tid < 128) s_jt[tid] = g_rslot[b*Rn + rBase + tid];

    int wm = (warp >> 2) * 64;      // 0 / 64
    int wn = (warp & 3) * 32;       // 0 / 32 / 64 / 96
    int wq = warp & 3;

    float acc[4][4][4];
    #pragma unroll
    for (int mt = 0; mt < 4; mt++)
        #pragma unroll
        for (int nt = 0; nt < 4; nt++)
            #pragma unroll
            for (int q = 0; q < 4; q++) acc[mt][nt][q] = 0.f;

    uint32_t sBase = smem_u32(smem);
    const uint32_t stageBytes = 2u * STAGE_ELE * 2u;  // A+B per stage
    const uint32_t sBoff = STAGE_ELE * 2u;

    int aRow = (lane & 15);
    int aColOff = (lane >> 4) * 8;
    int bN = (lane & 7) + ((lane >> 4) << 3);
    int bKOff = ((lane >> 3) & 1) * 8;

    int srow[4], scol[4];
    #pragma unroll
    for (int jj = 0; jj < 4; jj++) {
        int i = tid + jj*256;
        srow[jj] = i >> 3; scol[jj] = i & 7;
    }

    #define ISSUE(kc, stg) { \
        uint32_t d0 = sBase + (stg)*stageBytes; \
        _Pragma("unroll") \
        for (int jj = 0; jj < 4; jj++) { \
            uint32_t off = (srow[jj]*PAD + scol[jj]*8) * 2; \
            cp16(d0 + off,          A  + (size_t)srow[jj]*Dn + (kc)*64 + scol[jj]*8); \
            cp16(d0 + sBoff + off,  Bp + (size_t)srow[jj]*Dn + (kc)*64 + scol[jj]*8); \
        } \
        cp_commit(); \
    }

    ISSUE(0, 0);
    for (int kc = 0; kc < 4; kc++) {
        if (kc) __syncthreads();
        if (kc < 3) ISSUE(kc + 1, (kc + 1) & 1);
        if (kc < 3) cp_wait<1>(); else cp_wait<0>();
        __syncthreads();
        uint32_t sAu = sBase + (kc & 1)*stageBytes;
        uint32_t sBu = sAu + sBoff;
        #pragma unroll
        for (int ks = 0; ks < 4; ks++) {
            int kk = ks * 16;
            uint32_t a[4][4];
            #pragma unroll
            for (int mt = 0; mt < 4; mt++) {
                int row = wm + mt*16 + aRow;
                ldm_x4(a[mt], sAu + (row*PAD + kk + aColOff) * 2);
            }
            uint32_t bb[2][4];
            #pragma unroll
            for (int p = 0; p < 2; p++) {
                int n = wn + p*16 + bN;
                ldm_x4(bb[p], sBu + (n*PAD + kk + bKOff) * 2);
            }
            #pragma unroll
            for (int mt = 0; mt < 4; mt++)
                #pragma unroll
                for (int nt = 0; nt < 4; nt++)
                    mma_bf16(acc[mt][nt], a[mt],
                             bb[nt >> 1][(nt & 1)*2], bb[nt >> 1][(nt & 1)*2 + 1]);
        }
    }

    // ---- fused epilogue: per-row partial (max, sumexp) over this 128-col chunk ----
    int nu = g_nuniq[b];
    int tg = lane >> 2, ti = lane & 3;
    #pragma unroll
    for (int mt = 0; mt < 4; mt++) {
        #pragma unroll
        for (int h = 0; h < 2; h++) {
            int rowL = wm + mt*16 + tg + h*8;
            int jt = s_jt[rowL];
            float vals[8];
            float vmax = -1e30f;
            #pragma unroll
            for (int nt = 0; nt < 4; nt++) {
                #pragma unroll
                for (int ql = 0; ql < 2; ql++) {
                    int j = jBase + wn + nt*8 + ti*2 + ql;
                    float v = acc[mt][nt][h*2 + ql];
                    if (j == jt) g_tgt[b*Rn + rBase + rowL] = v;
                    float vv = (j < nu) ? v : -1e30f;
                    vals[nt*2 + ql] = vv;
                    vmax = fmaxf(vmax, vv);
                }
            }
            vmax = fmaxf(vmax, __shfl_xor_sync(0xffffffffu, vmax, 1));
            vmax = fmaxf(vmax, __shfl_xor_sync(0xffffffffu, vmax, 2));
            float se = 0.f;
            #pragma unroll
            for (int q = 0; q < 8; q++) se += __expf(vals[q] - vmax);
            se += __shfl_xor_sync(0xffffffffu, se, 1);
            se += __shfl_xor_sync(0xffffffffu, se, 2);
            if (ti == 0) { s_m[wq][rowL] = vmax; s_s[wq][rowL] = se; }
        }
    }
    __syncthreads();
    if (tid < 128) {
        float m0 = s_m[0][tid], m1 = s_m[1][tid], m2 = s_m[2][tid], m3 = s_m[3][tid];
        float m = fmaxf(fmaxf(m0, m1), fmaxf(m2, m3));
        float s = s_s[0][tid]*__expf(m0 - m) + s_s[1][tid]*__expf(m1 - m)
                + s_s[2][tid]*__expf(m2 - m) + s_s[3][tid]*__expf(m3 - m);
        int roi = b*Rn + rBase + tid;
        g_pm[roi*4 + blockIdx.x] = m;
        g_ps[roi*4 + blockIdx.x] = s;
    }
}

// ---------------- 5: combine partials + NLL + mean (single block) ----------------
__global__ void k_final(float* __restrict__ out) {
    __shared__ float ssum[512];
    __shared__ int   scnt[512];
    float sum = 0.f; int cnt = 0;
    for (int i = threadIdx.x; i < NROWS; i += 512) {
        int jt = g_rslot[i];
        if (jt >= 0) {
            float4 pm = *(const float4*)&g_pm[i*4];
            float4 ps = *(const float4*)&g_ps[i*4];
            float m = fmaxf(fmaxf(pm.x, pm.y), fmaxf(pm.z, pm.w));
            float s = ps.x*__expf(pm.x - m) + ps.y*__expf(pm.y - m)
                    + ps.z*__expf(pm.z - m) + ps.w*__expf(pm.w - m);
            sum += (m + logf(s)) - g_tgt[i];
            cnt++;
        }
    }
    ssum[threadIdx.x] = sum; scnt[threadIdx.x] = cnt;
    __syncthreads();
    for (int o = 256; o > 0; o >>= 1) {
        if (threadIdx.x < o) {
            ssum[threadIdx.x] += ssum[threadIdx.x + o];
            scnt[threadIdx.x] += scnt[threadIdx.x + o];
        }
        __syncthreads();
    }
    if (threadIdx.x == 0)
        out[0] = ssum[0] / fmaxf((float)scnt[0], 1.0f);
}

extern "C" void kernel_launch(void* const* d_in, const int* in_sizes, int n_in,
                              void* d_out, int out_size) {
    const float* inp = (const float*)d_in[0];
    const float* cls = (const float*)d_in[1];
    const int*   lab = (const int*)d_in[2];
    float* out = (float*)d_out;

    const int gemmSmem = 2 * 2 * STAGE_ELE * 2;  // 73728 bytes
    cudaFuncSetAttribute(k_gemm_mma, cudaFuncAttributeMaxDynamicSharedMemorySize, gemmSmem);

    k_prep<<<NROWS*Dn/4/256, 256>>>(inp, cls);
    k_compact<<<Bn, 256>>>(lab);
    k_norm<<<Bn*SLOT/8, 256>>>();
    k_gemm_mma<<<dim3(SLOT/128, Rn/128, Bn), 256, gemmSmem>>>();
    k_final<<<1, 512>>>(out);
}

// round 10
// speedup vs baseline: 3.6342x; 1.3443x over previous
#include <cuda_runtime.h>
#include <cuda_bf16.h>
#include <cstdint>
#include <math.h>

#define Bn 32
#define Rn 512
#define Dn 256
#define Pn 5532
#define SLOT 512
#define NROWS (Bn*Rn)
#define PAD 72                 // bf16 row stride in smem (64 + 8)
#define STAGE_ELE (128*PAD)    // elements per tile per stage

// ---------------- scratch ----------------
__device__ __align__(16) __nv_bfloat16 g_xh[NROWS*Dn];       // scaled feats bf16  8MB
__device__ __align__(16) __nv_bfloat16 g_ph[Bn*SLOT*Dn];     // normed protos bf16 8MB
__device__ __align__(16) float g_pm[NROWS*4];                // per-chunk row max
__device__ __align__(16) float g_ps[NROWS*4];                // per-chunk row sumexp
__device__ float g_tgt[NROWS];                               // target logit
__device__ int   g_rslot[NROWS];                             // roi -> slot (-1 bg)
__device__ int   g_sorted[NROWS];                            // rois sorted by slot (per image)
__device__ int   g_cnt[Bn*SLOT];                             // count per slot
__device__ int   g_cstart[Bn*SLOT];                          // member start per slot
__device__ int   g_nuniq[Bn];

// ---------------- helpers ----------------
__device__ __forceinline__ uint32_t smem_u32(const void* p) {
    uint32_t a;
    asm("{ .reg .u64 t; cvta.to.shared.u64 t, %1; cvt.u32.u64 %0, t; }" : "=r"(a) : "l"(p));
    return a;
}
__device__ __forceinline__ void cp16(uint32_t dst, const void* src) {
    asm volatile("cp.async.cg.shared.global [%0], [%1], 16;" :: "r"(dst), "l"(src));
}
__device__ __forceinline__ void cp_commit() {
    asm volatile("cp.async.commit_group;" ::: "memory");
}
template<int N> __device__ __forceinline__ void cp_wait() {
    asm volatile("cp.async.wait_group %0;" :: "n"(N) : "memory");
}
__device__ __forceinline__ void ldm_x4(uint32_t* r, uint32_t addr) {
    asm volatile("ldmatrix.sync.aligned.m8n8.x4.shared.b16 {%0,%1,%2,%3}, [%4];"
        : "=r"(r[0]), "=r"(r[1]), "=r"(r[2]), "=r"(r[3]) : "r"(addr));
}
__device__ __forceinline__ void mma_bf16(float* c, const uint32_t* a, uint32_t b0, uint32_t b1) {
    asm volatile(
        "mma.sync.aligned.m16n8k16.row.col.f32.bf16.bf16.f32 "
        "{%0,%1,%2,%3}, {%4,%5,%6,%7}, {%8,%9}, {%0,%1,%2,%3};"
        : "+f"(c[0]), "+f"(c[1]), "+f"(c[2]), "+f"(c[3])
        : "r"(a[0]), "r"(a[1]), "r"(a[2]), "r"(a[3]), "r"(b0), "r"(b1));
}
__device__ __forceinline__ unsigned long long pack4bf(float a, float b, float c, float d) {
    __nv_bfloat162 lo = __floats2bfloat162_rn(a, b);
    __nv_bfloat162 hi = __floats2bfloat162_rn(c, d);
    unsigned int l = *reinterpret_cast<unsigned int*>(&lo);
    unsigned int h = *reinterpret_cast<unsigned int*>(&hi);
    return (unsigned long long)l | ((unsigned long long)h << 32);
}

// ---------------- 1: fused [compact (blocks 0..31)] + [scale (blocks 32..2079)] -------
__global__ void k_prep_compact(const float* __restrict__ inp, const float* __restrict__ cls,
                               const int* __restrict__ roi_label) {
    __shared__ int cnt[Pn];          // counts, then pid -> slot id
    __shared__ int wU[8], wC[8];
    __shared__ int s_cur[SLOT];

    if (blockIdx.x >= Bn) {
        // ---- scale path: g_xh = bf16(inputs * cls) ----
        int i = (blockIdx.x - Bn) * 256 + threadIdx.x;   // float4 index
        int row = i >> 6;
        float c = cls[row];
        float4 v = ((const float4*)inp)[i];
        ((unsigned long long*)g_xh)[i] = pack4bf(v.x * c, v.y * c, v.z * c, v.w * c);
        return;
    }

    // ---- compact path ----
    int b = blockIdx.x;
    int tid = threadIdx.x;
    for (int p = tid; p < Pn; p += 256) cnt[p] = 0;
    __syncthreads();
    for (int r = tid; r < Rn; r += 256) {
        int lab = roi_label[b*Rn + r] - 1;
        if (lab >= 0) atomicAdd(&cnt[lab], 1);
    }
    __syncthreads();
    const int chunk = (Pn + 255) / 256;   // 22
    int start = tid * chunk;
    int lu = 0, lc = 0;
    for (int i = 0; i < chunk; i++) {
        int p = start + i;
        if (p < Pn) { int c = cnt[p]; if (c > 0) { lu++; lc += c; } }
    }
    // parallel exclusive scan over 256 threads (both lu and lc)
    int wlane = tid & 31, wwarp = tid >> 5;
    int iu = lu, ic = lc;
    #pragma unroll
    for (int o = 1; o < 32; o <<= 1) {
        int tu = __shfl_up_sync(0xffffffffu, iu, o);
        int tc = __shfl_up_sync(0xffffffffu, ic, o);
        if (wlane >= o) { iu += tu; ic += tc; }
    }
    if (wlane == 31) { wU[wwarp] = iu; wC[wwarp] = ic; }
    __syncthreads();
    if (tid == 0) {
        int au = 0, ac = 0;
        #pragma unroll
        for (int w = 0; w < 8; w++) {
            int tu = wU[w], tc = wC[w];
            wU[w] = au; wC[w] = ac;
            au += tu; ac += tc;
        }
        g_nuniq[b] = au;
    }
    __syncthreads();
    int off = iu - lu + wU[wwarp];     // exclusive prefix of unique-count
    int cst = ic - lc + wC[wwarp];     // exclusive prefix of member-count
    for (int i = 0; i < chunk; i++) {
        int p = start + i;
        if (p >= Pn) break;
        int c = cnt[p];
        if (c > 0) {
            g_cnt[b*SLOT + off]    = c;
            g_cstart[b*SLOT + off] = cst;
            s_cur[off] = cst;
            cnt[p] = off;
            off++; cst += c;
        } else {
            cnt[p] = -1;
        }
    }
    __syncthreads();
    for (int r = tid; r < Rn; r += 256) {
        int lab = roi_label[b*Rn + r] - 1;
        int slot = (lab >= 0) ? cnt[lab] : -1;
        g_rslot[b*Rn + r] = slot;
        if (slot >= 0) {
            int pos = atomicAdd(&s_cur[slot], 1);
            g_sorted[b*Rn + pos] = r;
        }
    }
}

// ---------------- 2: proto gather + normalize -> bf16 (one warp per slot) ----------------
__global__ void k_norm() {
    int idx  = blockIdx.x * 8 + (threadIdx.x >> 5);
    int lane = threadIdx.x & 31;
    int b = idx / SLOT, j = idx % SLOT;
    uint4* dst = (uint4*)(g_ph + (size_t)idx * Dn);   // 32 lanes x 16B = 512B row
    if (j >= g_nuniq[b]) {
        dst[lane] = make_uint4(0, 0, 0, 0);
        return;
    }
    int c  = g_cnt[b*SLOT + j];
    int st = g_cstart[b*SLOT + j];
    float acc[8];
    #pragma unroll
    for (int q = 0; q < 8; q++) acc[q] = 0.f;
    for (int m = 0; m < c; m++) {
        int r = g_sorted[b*Rn + st + m];
        uint4 v = ((const uint4*)(g_xh + (size_t)(b*Rn + r) * Dn))[lane];
        uint32_t w[4] = {v.x, v.y, v.z, v.w};
        #pragma unroll
        for (int q = 0; q < 4; q++) {
            float2 f = __bfloat1622float2(*(__nv_bfloat162*)&w[q]);
            acc[q*2]   += f.x;
            acc[q*2+1] += f.y;
        }
    }
    float ss = 0.f;
    #pragma unroll
    for (int q = 0; q < 8; q++) ss += acc[q]*acc[q];
    #pragma unroll
    for (int o = 16; o > 0; o >>= 1) ss += __shfl_xor_sync(0xffffffffu, ss, o);
    float cf = (float)c;
    float scale = 1.0f / (cf * fmaxf(sqrtf(ss) / cf, 1e-12f));
    uint32_t o0, o1, o2, o3;
    {
        __nv_bfloat162 p0 = __floats2bfloat162_rn(acc[0]*scale, acc[1]*scale);
        __nv_bfloat162 p1 = __floats2bfloat162_rn(acc[2]*scale, acc[3]*scale);
        __nv_bfloat162 p2 = __floats2bfloat162_rn(acc[4]*scale, acc[5]*scale);
        __nv_bfloat162 p3 = __floats2bfloat162_rn(acc[6]*scale, acc[7]*scale);
        o0 = *(uint32_t*)&p0; o1 = *(uint32_t*)&p1; o2 = *(uint32_t*)&p2; o3 = *(uint32_t*)&p3;
    }
    dst[lane] = make_uint4(o0, o1, o2, o3);
}

// ---------------- 3: bf16 mma.sync GEMM (cp.async 2-stage) + fused softmax partials --
__global__ __launch_bounds__(256, 2) void k_gemm_mma() {
    extern __shared__ __nv_bfloat16 smem[];      // [2][sA 128*PAD | sB 128*PAD]
    __shared__ int   s_jt[128];
    __shared__ float s_m[4][128];
    __shared__ float s_s[4][128];
    int tid = threadIdx.x;
    int warp = tid >> 5, lane = tid & 31;
    int b = blockIdx.z;
    int rBase = blockIdx.y * 128;
    int jBase = blockIdx.x * 128;
    const __nv_bfloat16* A  = g_xh + ((size_t)b*Rn   + rBase) * Dn;
    const __nv_bfloat16* Bp = g_ph + ((size_t)b*SLOT + jBase) * Dn;

    if (tid < 128) s_jt[tid] = g_rslot[b*Rn + rBase + tid];

    int wm = (warp >> 2) * 64;      // 0 / 64
    int wn = (warp & 3) * 32;       // 0 / 32 / 64 / 96
    int wq = warp & 3;

    float acc[4][4][4];
    #pragma unroll
    for (int mt = 0; mt < 4; mt++)
        #pragma unroll
        for (int nt = 0; nt < 4; nt++)
            #pragma unroll
            for (int q = 0; q < 4; q++) acc[mt][nt][q] = 0.f;

    uint32_t sBase = smem_u32(smem);
    const uint32_t stageBytes = 2u * STAGE_ELE * 2u;  // A+B per stage
    const uint32_t sBoff = STAGE_ELE * 2u;

    int aRow = (lane & 15);
    int aColOff = (lane >> 4) * 8;
    int bN = (lane & 7) + ((lane >> 4) << 3);
    int bKOff = ((lane >> 3) & 1) * 8;

    int srow[4], scol[4];
    #pragma unroll
    for (int jj = 0; jj < 4; jj++) {
        int i = tid + jj*256;
        srow[jj] = i >> 3; scol[jj] = i & 7;
    }

    #define ISSUE(kc, stg) { \
        uint32_t d0 = sBase + (stg)*stageBytes; \
        _Pragma("unroll") \
        for (int jj = 0; jj < 4; jj++) { \
            uint32_t off = (srow[jj]*PAD + scol[jj]*8) * 2; \
            cp16(d0 + off,          A  + (size_t)srow[jj]*Dn + (kc)*64 + scol[jj]*8); \
            cp16(d0 + sBoff + off,  Bp + (size_t)srow[jj]*Dn + (kc)*64 + scol[jj]*8); \
        } \
        cp_commit(); \
    }

    ISSUE(0, 0);
    for (int kc = 0; kc < 4; kc++) {
        if (kc) __syncthreads();
        if (kc < 3) ISSUE(kc + 1, (kc + 1) & 1);
        if (kc < 3) cp_wait<1>(); else cp_wait<0>();
        __syncthreads();
        uint32_t sAu = sBase + (kc & 1)*stageBytes;
        uint32_t sBu = sAu + sBoff;
        #pragma unroll
        for (int ks = 0; ks < 4; ks++) {
            int kk = ks * 16;
            uint32_t a[4][4];
            #pragma unroll
            for (int mt = 0; mt < 4; mt++) {
                int row = wm + mt*16 + aRow;
                ldm_x4(a[mt], sAu + (row*PAD + kk + aColOff) * 2);
            }
            uint32_t bb[2][4];
            #pragma unroll
            for (int p = 0; p < 2; p++) {
                int n = wn + p*16 + bN;
                ldm_x4(bb[p], sBu + (n*PAD + kk + bKOff) * 2);
            }
            #pragma unroll
            for (int mt = 0; mt < 4; mt++)
                #pragma unroll
                for (int nt = 0; nt < 4; nt++)
                    mma_bf16(acc[mt][nt], a[mt],
                             bb[nt >> 1][(nt & 1)*2], bb[nt >> 1][(nt & 1)*2 + 1]);
        }
    }

    // ---- fused epilogue: per-row partial (max, sumexp) over this 128-col chunk ----
    int nu = g_nuniq[b];
    int tg = lane >> 2, ti = lane & 3;
    #pragma unroll
    for (int mt = 0; mt < 4; mt++) {
        #pragma unroll
        for (int h = 0; h < 2; h++) {
            int rowL = wm + mt*16 + tg + h*8;
            int jt = s_jt[rowL];
            float vals[8];
            float vmax = -1e30f;
            #pragma unroll
            for (int nt = 0; nt < 4; nt++) {
                #pragma unroll
                for (int ql = 0; ql < 2; ql++) {
                    int j = jBase + wn + nt*8 + ti*2 + ql;
                    float v = acc[mt][nt][h*2 + ql];
                    if (j == jt) g_tgt[b*Rn + rBase + rowL] = v;
                    float vv = (j < nu) ? v : -1e30f;
                    vals[nt*2 + ql] = vv;
                    vmax = fmaxf(vmax, vv);
                }
            }
            vmax = fmaxf(vmax, __shfl_xor_sync(0xffffffffu, vmax, 1));
            vmax = fmaxf(vmax, __shfl_xor_sync(0xffffffffu, vmax, 2));
            float se = 0.f;
            #pragma unroll
            for (int q = 0; q < 8; q++) se += __expf(vals[q] - vmax);
            se += __shfl_xor_sync(0xffffffffu, se, 1);
            se += __shfl_xor_sync(0xffffffffu, se, 2);
            if (ti == 0) { s_m[wq][rowL] = vmax; s_s[wq][rowL] = se; }
        }
    }
    __syncthreads();
    if (tid < 128) {
        float m0 = s_m[0][tid], m1 = s_m[1][tid], m2 = s_m[2][tid], m3 = s_m[3][tid];
        float m = fmaxf(fmaxf(m0, m1), fmaxf(m2, m3));
        float s = s_s[0][tid]*__expf(m0 - m) + s_s[1][tid]*__expf(m1 - m)
                + s_s[2][tid]*__expf(m2 - m) + s_s[3][tid]*__expf(m3 - m);
        int roi = b*Rn + rBase + tid;
        g_pm[roi*4 + blockIdx.x] = m;
        g_ps[roi*4 + blockIdx.x] = s;
    }
}

// ---------------- 4: combine partials + NLL + mean (single block, 1024 thr) ----------
__global__ void k_final(float* __restrict__ out) {
    __shared__ float ssum[1024];
    __shared__ int   scnt[1024];
    float sum = 0.f; int cnt = 0;
    for (int i = threadIdx.x; i < NROWS; i += 1024) {
        int jt = g_rslot[i];
        if (jt >= 0) {
            float4 pm = *(const float4*)&g_pm[i*4];
            float4 ps = *(const float4*)&g_ps[i*4];
            float m = fmaxf(fmaxf(pm.x, pm.y), fmaxf(pm.z, pm.w));
            float s = ps.x*__expf(pm.x - m) + ps.y*__expf(pm.y - m)
                    + ps.z*__expf(pm.z - m) + ps.w*__expf(pm.w - m);
            sum += (m + logf(s)) - g_tgt[i];
            cnt++;
        }
    }
    ssum[threadIdx.x] = sum; scnt[threadIdx.x] = cnt;
    __syncthreads();
    for (int o = 512; o > 0; o >>= 1) {
        if (threadIdx.x < o) {
            ssum[threadIdx.x] += ssum[threadIdx.x + o];
            scnt[threadIdx.x] += scnt[threadIdx.x + o];
        }
        __syncthreads();
    }
    if (threadIdx.x == 0)
        out[0] = ssum[0] / fmaxf((float)scnt[0], 1.0f);
}

extern "C" void kernel_launch(void* const* d_in, const int* in_sizes, int n_in,
                              void* d_out, int out_size) {
    const float* inp = (const float*)d_in[0];
    const float* cls = (const float*)d_in[1];
    const int*   lab = (const int*)d_in[2];
    float* out = (float*)d_out;

    const int gemmSmem = 2 * 2 * STAGE_ELE * 2;  // 73728 bytes
    cudaFuncSetAttribute(k_gemm_mma, cudaFuncAttributeMaxDynamicSharedMemorySize, gemmSmem);

    k_prep_compact<<<Bn + NROWS*Dn/4/256, 256>>>(inp, cls, lab);
    k_norm<<<Bn*SLOT/8, 256>>>();
    k_gemm_mma<<<dim3(SLOT/128, Rn/128, Bn), 256, gemmSmem>>>();
    k_final<<<1, 1024>>>(out);
}

// round 11
// speedup vs baseline: 4.3793x; 1.2050x over previous
#include <cuda_runtime.h>
#include <cuda_bf16.h>
#include <cstdint>
#include <math.h>

#define Bn 32
#define Rn 512
#define Dn 256
#define Pn 5532
#define SLOT 512
#define NROWS (Bn*Rn)
#define PAD 72                 // bf16 row stride in smem (64 + 8)
#define STAGE_ELE (128*PAD)    // elements per tile per stage

// ---------------- scratch ----------------
__device__ __align__(16) __nv_bfloat16 g_xh[NROWS*Dn];       // scaled feats bf16  8MB
__device__ __align__(16) __nv_bfloat16 g_ph[Bn*SLOT*Dn];     // normed protos bf16 8MB
__device__ __align__(16) float g_pm[NROWS*4];                // per-chunk row max
__device__ __align__(16) float g_ps[NROWS*4];                // per-chunk row sumexp
__device__ float g_tgt[NROWS];                               // target logit
__device__ int   g_rslot[NROWS];                             // roi -> slot (-1 bg)
__device__ int   g_sorted[NROWS];                            // rois sorted by slot (per image)
__device__ int   g_cnt[Bn*SLOT];                             // count per slot
__device__ int   g_cstart[Bn*SLOT];                          // member start per slot
__device__ int   g_nuniq[Bn];
__device__ float g_bsum[Bn];                                 // per-image nll sum
__device__ int   g_bcnt[Bn];                                 // per-image valid count

// ---------------- helpers ----------------
__device__ __forceinline__ uint32_t smem_u32(const void* p) {
    uint32_t a;
    asm("{ .reg .u64 t; cvta.to.shared.u64 t, %1; cvt.u32.u64 %0, t; }" : "=r"(a) : "l"(p));
    return a;
}
__device__ __forceinline__ void cp16(uint32_t dst, const void* src) {
    asm volatile("cp.async.cg.shared.global [%0], [%1], 16;" :: "r"(dst), "l"(src));
}
__device__ __forceinline__ void cp_commit() {
    asm volatile("cp.async.commit_group;" ::: "memory");
}
template<int N> __device__ __forceinline__ void cp_wait() {
    asm volatile("cp.async.wait_group %0;" :: "n"(N) : "memory");
}
__device__ __forceinline__ void ldm_x4(uint32_t* r, uint32_t addr) {
    asm volatile("ldmatrix.sync.aligned.m8n8.x4.shared.b16 {%0,%1,%2,%3}, [%4];"
        : "=r"(r[0]), "=r"(r[1]), "=r"(r[2]), "=r"(r[3]) : "r"(addr));
}
__device__ __forceinline__ void mma_bf16(float* c, const uint32_t* a, uint32_t b0, uint32_t b1) {
    asm volatile(
        "mma.sync.aligned.m16n8k16.row.col.f32.bf16.bf16.f32 "
        "{%0,%1,%2,%3}, {%4,%5,%6,%7}, {%8,%9}, {%0,%1,%2,%3};"
        : "+f"(c[0]), "+f"(c[1]), "+f"(c[2]), "+f"(c[3])
        : "r"(a[0]), "r"(a[1]), "r"(a[2]), "r"(a[3]), "r"(b0), "r"(b1));
}
__device__ __forceinline__ unsigned long long pack4bf(float a, float b, float c, float d) {
    __nv_bfloat162 lo = __floats2bfloat162_rn(a, b);
    __nv_bfloat162 hi = __floats2bfloat162_rn(c, d);
    unsigned int l = *reinterpret_cast<unsigned int*>(&lo);
    unsigned int h = *reinterpret_cast<unsigned int*>(&hi);
    return (unsigned long long)l | ((unsigned long long)h << 32);
}

// ---------------- 1: fused [compact (blocks 0..31)] + [scale (blocks 32..2079)] -------
__global__ void k_prep_compact(const float* __restrict__ inp, const float* __restrict__ cls,
                               const int* __restrict__ roi_label) {
    __shared__ int cnt[Pn];          // counts, then pid -> slot id
    __shared__ int wU[8], wC[8];
    __shared__ int s_cur[SLOT];

    if (blockIdx.x >= Bn) {
        // ---- scale path: g_xh = bf16(inputs * cls) ----
        int i = (blockIdx.x - Bn) * 256 + threadIdx.x;   // float4 index
        int row = i >> 6;
        float c = cls[row];
        float4 v = ((const float4*)inp)[i];
        ((unsigned long long*)g_xh)[i] = pack4bf(v.x * c, v.y * c, v.z * c, v.w * c);
        return;
    }

    // ---- compact path ----
    int b = blockIdx.x;
    int tid = threadIdx.x;
    for (int p = tid; p < Pn; p += 256) cnt[p] = 0;
    __syncthreads();
    for (int r = tid; r < Rn; r += 256) {
        int lab = roi_label[b*Rn + r] - 1;
        if (lab >= 0) atomicAdd(&cnt[lab], 1);
    }
    __syncthreads();
    const int chunk = (Pn + 255) / 256;   // 22
    int start = tid * chunk;
    int lu = 0, lc = 0;
    for (int i = 0; i < chunk; i++) {
        int p = start + i;
        if (p < Pn) { int c = cnt[p]; if (c > 0) { lu++; lc += c; } }
    }
    // parallel exclusive scan over 256 threads (both lu and lc)
    int wlane = tid & 31, wwarp = tid >> 5;
    int iu = lu, ic = lc;
    #pragma unroll
    for (int o = 1; o < 32; o <<= 1) {
        int tu = __shfl_up_sync(0xffffffffu, iu, o);
        int tc = __shfl_up_sync(0xffffffffu, ic, o);
        if (wlane >= o) { iu += tu; ic += tc; }
    }
    if (wlane == 31) { wU[wwarp] = iu; wC[wwarp] = ic; }
    __syncthreads();
    if (tid == 0) {
        int au = 0, ac = 0;
        #pragma unroll
        for (int w = 0; w < 8; w++) {
            int tu = wU[w], tc = wC[w];
            wU[w] = au; wC[w] = ac;
            au += tu; ac += tc;
        }
        g_nuniq[b] = au;
    }
    __syncthreads();
    int off = iu - lu + wU[wwarp];     // exclusive prefix of unique-count
    int cst = ic - lc + wC[wwarp];     // exclusive prefix of member-count
    for (int i = 0; i < chunk; i++) {
        int p = start + i;
        if (p >= Pn) break;
        int c = cnt[p];
        if (c > 0) {
            g_cnt[b*SLOT + off]    = c;
            g_cstart[b*SLOT + off] = cst;
            s_cur[off] = cst;
            cnt[p] = off;
            off++; cst += c;
        } else {
            cnt[p] = -1;
        }
    }
    __syncthreads();
    for (int r = tid; r < Rn; r += 256) {
        int lab = roi_label[b*Rn + r] - 1;
        int slot = (lab >= 0) ? cnt[lab] : -1;
        g_rslot[b*Rn + r] = slot;
        if (slot >= 0) {
            int pos = atomicAdd(&s_cur[slot], 1);
            g_sorted[b*Rn + pos] = r;
        }
    }
}

// ---------------- 2: proto gather + normalize -> bf16 (one warp per slot) ----------------
__global__ void k_norm() {
    int idx  = blockIdx.x * 8 + (threadIdx.x >> 5);
    int lane = threadIdx.x & 31;
    int b = idx / SLOT, j = idx % SLOT;
    uint4* dst = (uint4*)(g_ph + (size_t)idx * Dn);   // 32 lanes x 16B = 512B row
    if (j >= g_nuniq[b]) {
        dst[lane] = make_uint4(0, 0, 0, 0);
        return;
    }
    int c  = g_cnt[b*SLOT + j];
    int st = g_cstart[b*SLOT + j];
    float acc[8];
    #pragma unroll
    for (int q = 0; q < 8; q++) acc[q] = 0.f;
    for (int m = 0; m < c; m++) {
        int r = g_sorted[b*Rn + st + m];
        uint4 v = ((const uint4*)(g_xh + (size_t)(b*Rn + r) * Dn))[lane];
        uint32_t w[4] = {v.x, v.y, v.z, v.w};
        #pragma unroll
        for (int q = 0; q < 4; q++) {
            float2 f = __bfloat1622float2(*(__nv_bfloat162*)&w[q]);
            acc[q*2]   += f.x;
            acc[q*2+1] += f.y;
        }
    }
    float ss = 0.f;
    #pragma unroll
    for (int q = 0; q < 8; q++) ss += acc[q]*acc[q];
    #pragma unroll
    for (int o = 16; o > 0; o >>= 1) ss += __shfl_xor_sync(0xffffffffu, ss, o);
    float cf = (float)c;
    float scale = 1.0f / (cf * fmaxf(sqrtf(ss) / cf, 1e-12f));
    uint32_t o0, o1, o2, o3;
    {
        __nv_bfloat162 p0 = __floats2bfloat162_rn(acc[0]*scale, acc[1]*scale);
        __nv_bfloat162 p1 = __floats2bfloat162_rn(acc[2]*scale, acc[3]*scale);
        __nv_bfloat162 p2 = __floats2bfloat162_rn(acc[4]*scale, acc[5]*scale);
        __nv_bfloat162 p3 = __floats2bfloat162_rn(acc[6]*scale, acc[7]*scale);
        o0 = *(uint32_t*)&p0; o1 = *(uint32_t*)&p1; o2 = *(uint32_t*)&p2; o3 = *(uint32_t*)&p3;
    }
    dst[lane] = make_uint4(o0, o1, o2, o3);
}

// ---------------- 3: bf16 mma.sync GEMM (cp.async 2-stage) + fused softmax partials --
__global__ __launch_bounds__(256, 2) void k_gemm_mma() {
    extern __shared__ __nv_bfloat16 smem[];      // [2][sA 128*PAD | sB 128*PAD]
    __shared__ int   s_jt[128];
    __shared__ float s_m[4][128];
    __shared__ float s_s[4][128];
    int tid = threadIdx.x;
    int warp = tid >> 5, lane = tid & 31;
    int b = blockIdx.z;
    int rBase = blockIdx.y * 128;
    int jBase = blockIdx.x * 128;
    const __nv_bfloat16* A  = g_xh + ((size_t)b*Rn   + rBase) * Dn;
    const __nv_bfloat16* Bp = g_ph + ((size_t)b*SLOT + jBase) * Dn;

    if (tid < 128) s_jt[tid] = g_rslot[b*Rn + rBase + tid];

    int wm = (warp >> 2) * 64;      // 0 / 64
    int wn = (warp & 3) * 32;       // 0 / 32 / 64 / 96
    int wq = warp & 3;

    float acc[4][4][4];
    #pragma unroll
    for (int mt = 0; mt < 4; mt++)
        #pragma unroll
        for (int nt = 0; nt < 4; nt++)
            #pragma unroll
            for (int q = 0; q < 4; q++) acc[mt][nt][q] = 0.f;

    uint32_t sBase = smem_u32(smem);
    const uint32_t stageBytes = 2u * STAGE_ELE * 2u;  // A+B per stage
    const uint32_t sBoff = STAGE_ELE * 2u;

    int aRow = (lane & 15);
    int aColOff = (lane >> 4) * 8;
    int bN = (lane & 7) + ((lane >> 4) << 3);
    int bKOff = ((lane >> 3) & 1) * 8;

    int srow[4], scol[4];
    #pragma unroll
    for (int jj = 0; jj < 4; jj++) {
        int i = tid + jj*256;
        srow[jj] = i >> 3; scol[jj] = i & 7;
    }

    #define ISSUE(kc, stg) { \
        uint32_t d0 = sBase + (stg)*stageBytes; \
        _Pragma("unroll") \
        for (int jj = 0; jj < 4; jj++) { \
            uint32_t off = (srow[jj]*PAD + scol[jj]*8) * 2; \
            cp16(d0 + off,          A  + (size_t)srow[jj]*Dn + (kc)*64 + scol[jj]*8); \
            cp16(d0 + sBoff + off,  Bp + (size_t)srow[jj]*Dn + (kc)*64 + scol[jj]*8); \
        } \
        cp_commit(); \
    }

    ISSUE(0, 0);
    for (int kc = 0; kc < 4; kc++) {
        if (kc) __syncthreads();
        if (kc < 3) ISSUE(kc + 1, (kc + 1) & 1);
        if (kc < 3) cp_wait<1>(); else cp_wait<0>();
        __syncthreads();
        uint32_t sAu = sBase + (kc & 1)*stageBytes;
        uint32_t sBu = sAu + sBoff;
        #pragma unroll
        for (int ks = 0; ks < 4; ks++) {
            int kk = ks * 16;
            uint32_t a[4][4];
            #pragma unroll
            for (int mt = 0; mt < 4; mt++) {
                int row = wm + mt*16 + aRow;
                ldm_x4(a[mt], sAu + (row*PAD + kk + aColOff) * 2);
            }
            uint32_t bb[2][4];
            #pragma unroll
            for (int p = 0; p < 2; p++) {
                int n = wn + p*16 + bN;
                ldm_x4(bb[p], sBu + (n*PAD + kk + bKOff) * 2);
            }
            #pragma unroll
            for (int mt = 0; mt < 4; mt++)
                #pragma unroll
                for (int nt = 0; nt < 4; nt++)
                    mma_bf16(acc[mt][nt], a[mt],
                             bb[nt >> 1][(nt & 1)*2], bb[nt >> 1][(nt & 1)*2 + 1]);
        }
    }

    // ---- fused epilogue: per-row partial (max, sumexp) over this 128-col chunk ----
    int nu = g_nuniq[b];
    int tg = lane >> 2, ti = lane & 3;
    #pragma unroll
    for (int mt = 0; mt < 4; mt++) {
        #pragma unroll
        for (int h = 0; h < 2; h++) {
            int rowL = wm + mt*16 + tg + h*8;
            int jt = s_jt[rowL];
            float vals[8];
            float vmax = -1e30f;
            #pragma unroll
            for (int nt = 0; nt < 4; nt++) {
                #pragma unroll
                for (int ql = 0; ql < 2; ql++) {
                    int j = jBase + wn + nt*8 + ti*2 + ql;
                    float v = acc[mt][nt][h*2 + ql];
                    if (j == jt) g_tgt[b*Rn + rBase + rowL] = v;
                    float vv = (j < nu) ? v : -1e30f;
                    vals[nt*2 + ql] = vv;
                    vmax = fmaxf(vmax, vv);
                }
            }
            vmax = fmaxf(vmax, __shfl_xor_sync(0xffffffffu, vmax, 1));
            vmax = fmaxf(vmax, __shfl_xor_sync(0xffffffffu, vmax, 2));
            float se = 0.f;
            #pragma unroll
            for (int q = 0; q < 8; q++) se += __expf(vals[q] - vmax);
            se += __shfl_xor_sync(0xffffffffu, se, 1);
            se += __shfl_xor_sync(0xffffffffu, se, 2);
            if (ti == 0) { s_m[wq][rowL] = vmax; s_s[wq][rowL] = se; }
        }
    }
    __syncthreads();
    if (tid < 128) {
        float m0 = s_m[0][tid], m1 = s_m[1][tid], m2 = s_m[2][tid], m3 = s_m[3][tid];
        float m = fmaxf(fmaxf(m0, m1), fmaxf(m2, m3));
        float s = s_s[0][tid]*__expf(m0 - m) + s_s[1][tid]*__expf(m1 - m)
                + s_s[2][tid]*__expf(m2 - m) + s_s[3][tid]*__expf(m3 - m);
        int roi = b*Rn + rBase + tid;
        g_pm[roi*4 + blockIdx.x] = m;
        g_ps[roi*4 + blockIdx.x] = s;
    }
}

// ---------------- 4a: per-image NLL partial reduce (one block per image) ----------
__global__ void k_nll_part() {
    __shared__ float ssum[16];
    __shared__ int   scnt[16];
    int b = blockIdx.x;
    int tid = threadIdx.x;                 // 512 threads, one per ROI
    int i = b*Rn + tid;
    float sum = 0.f; int cnt = 0;
    int jt = g_rslot[i];
    if (jt >= 0) {
        float4 pm = *(const float4*)&g_pm[i*4];
        float4 ps = *(const float4*)&g_ps[i*4];
        float m = fmaxf(fmaxf(pm.x, pm.y), fmaxf(pm.z, pm.w));
        float s = ps.x*__expf(pm.x - m) + ps.y*__expf(pm.y - m)
                + ps.z*__expf(pm.z - m) + ps.w*__expf(pm.w - m);
        sum = (m + logf(s)) - g_tgt[i];
        cnt = 1;
    }
    #pragma unroll
    for (int o = 16; o > 0; o >>= 1) {
        sum += __shfl_xor_sync(0xffffffffu, sum, o);
        cnt += __shfl_xor_sync(0xffffffffu, cnt, o);
    }
    if ((tid & 31) == 0) { ssum[tid >> 5] = sum; scnt[tid >> 5] = cnt; }
    __syncthreads();
    if (tid == 0) {
        float ts = 0.f; int tc = 0;
        #pragma unroll
        for (int w = 0; w < 16; w++) { ts += ssum[w]; tc += scnt[w]; }
        g_bsum[b] = ts; g_bcnt[b] = tc;
    }
}

// ---------------- 4b: combine 32 per-image partials ----------------
__global__ void k_final(float* __restrict__ out) {
    int lane = threadIdx.x;                // 32 threads
    float s = g_bsum[lane];
    int   c = g_bcnt[lane];
    #pragma unroll
    for (int o = 16; o > 0; o >>= 1) {
        s += __shfl_xor_sync(0xffffffffu, s, o);
        c += __shfl_xor_sync(0xffffffffu, c, o);
    }
    if (lane == 0)
        out[0] = s / fmaxf((float)c, 1.0f);
}

extern "C" void kernel_launch(void* const* d_in, const int* in_sizes, int n_in,
                              void* d_out, int out_size) {
    const float* inp = (const float*)d_in[0];
    const float* cls = (const float*)d_in[1];
    const int*   lab = (const int*)d_in[2];
    float* out = (float*)d_out;

    const int gemmSmem = 2 * 2 * STAGE_ELE * 2;  // 73728 bytes
    cudaFuncSetAttribute(k_gemm_mma, cudaFuncAttributeMaxDynamicSharedMemorySize, gemmSmem);

    k_prep_compact<<<Bn + NROWS*Dn/4/256, 256>>>(inp, cls, lab);
    k_norm<<<Bn*SLOT/8, 256>>>();
    k_gemm_mma<<<dim3(SLOT/128, Rn/128, Bn), 256, gemmSmem>>>();
    k_nll_part<<<Bn, Rn>>>();
    k_final<<<1, 32>>>(out);
}